// round 12
// baseline (speedup 1.0000x reference)
#include <cuda_runtime.h>

#define NN 50000
#define EE 500000
#define EPSF 1e-8f

typedef unsigned long long u64;

// ---------------- scratch (device globals) ----------------
__device__ __align__(16) float g_hedge[EE * 32];   // he (pass1) then m (pass2)
__device__ __align__(16) float g_expl[EE * 4];
__device__ __align__(16) float g_dir[EE * 4];
__device__ __align__(16) float g_denom[NN * 4];
__device__ __align__(16) float g_cnt[NN];
__device__ __align__(16) float g_sem[NN * 128];
__device__ __align__(16) float g_comb[NN * 96];
__device__ __align__(16) float g_P1[NN * 64];
__device__ __align__(16) float g_P2[NN * 64];
__device__ __align__(16) float g_Q1[NN * 20];
__device__ __align__(16) float g_Q2[NN * 20];
__device__ __align__(16) float g_spa[NN * 32];
__device__ __align__(16) float g_dv[NN * 4];
__device__ __align__(16) float g_z[(size_t)NN * 128];   // node-MLP hidden
// sorting infra
__device__ __align__(16) int g_icnt[NN + 256];
__device__ __align__(16) int g_rowstart[NN];
__device__ __align__(16) int g_woff[NN];
__device__ __align__(16) int2 g_sij[EE];
__device__ __align__(16) int g_bsum[256];
__device__ __align__(16) int g_boff[256];

// ---------------- helpers ----------------
__device__ __forceinline__ u64 pk2(float v) {
    u64 r; asm("mov.b64 %0,{%1,%1};" : "=l"(r) : "f"(v)); return r;
}
__device__ __forceinline__ u64 pk(float a, float b) {
    u64 r; asm("mov.b64 %0,{%1,%2};" : "=l"(r) : "f"(a), "f"(b)); return r;
}
__device__ __forceinline__ void fma2(u64 &d, u64 a, u64 b) {
    asm("fma.rn.f32x2 %0,%1,%2,%0;" : "+l"(d) : "l"(a), "l"(b));
}
__device__ __forceinline__ float2 upk(u64 v) {
    float2 f; asm("mov.b64 {%0,%1},%2;" : "=f"(f.x), "=f"(f.y) : "l"(v)); return f;
}
__device__ __forceinline__ float silu_(float z) { return z * (1.f / (1.f + __expf(-z))); }

// ---------------- K0: zero icnt ----------------
__global__ void k_zero() {
    int t = blockIdx.x * blockDim.x + threadIdx.x;
    if (t < NN + 256) g_icnt[t] = 0;
}

// ---------------- sort: histogram ----------------
__global__ void k_count(const int* __restrict__ idx_i) {
    int e = blockIdx.x * blockDim.x + threadIdx.x;
    if (e < EE) atomicAdd(&g_icnt[idx_i[e]], 1);
}

// ---------------- sort: block sums ----------------
__global__ void __launch_bounds__(256) k_scan_a() {
    __shared__ int s[256];
    int n = blockIdx.x * 256 + threadIdx.x;
    int v = (n < NN) ? g_icnt[n] : 0;
    s[threadIdx.x] = v;
    __syncthreads();
    #pragma unroll
    for (int off = 128; off > 0; off >>= 1) {
        if (threadIdx.x < off) s[threadIdx.x] += s[threadIdx.x + off];
        __syncthreads();
    }
    if (threadIdx.x == 0) g_bsum[blockIdx.x] = s[0];
}

// ---------------- sort: scan of block sums ----------------
__global__ void __launch_bounds__(256) k_scan_b(int nblocks) {
    __shared__ int s[256];
    int t = threadIdx.x;
    int v = (t < nblocks) ? g_bsum[t] : 0;
    s[t] = v;
    __syncthreads();
    #pragma unroll
    for (int off = 1; off < 256; off <<= 1) {
        int u = (t >= off) ? s[t - off] : 0;
        __syncthreads();
        s[t] += u;
        __syncthreads();
    }
    g_boff[t] = s[t] - v;   // exclusive
}

// ---------------- sort: per-block scan + offsets ----------------
__global__ void __launch_bounds__(256) k_scan_c() {
    __shared__ int s[256];
    int n = blockIdx.x * 256 + threadIdx.x;
    int c = (n < NN) ? g_icnt[n] : 0;
    int t = threadIdx.x;
    s[t] = c;
    __syncthreads();
    #pragma unroll
    for (int off = 1; off < 256; off <<= 1) {
        int u = (t >= off) ? s[t - off] : 0;
        __syncthreads();
        s[t] += u;
        __syncthreads();
    }
    if (n < NN) {
        int rs = g_boff[blockIdx.x] + s[t] - c;
        g_rowstart[n] = rs;
        g_woff[n] = rs;
        g_cnt[n] = (float)c;
    }
}

// ---------------- sort: scatter sorted (i,j) ----------------
__global__ void k_scatter(const int* __restrict__ idx_i, const int* __restrict__ idx_j) {
    int e = blockIdx.x * blockDim.x + threadIdx.x;
    if (e >= EE) return;
    int i = idx_i[e];
    int pos = atomicAdd(&g_woff[i], 1);
    g_sij[pos] = make_int2(i, idx_j[e]);
}

// ---------------- K_pre: per-node projections (now 2 blocks/SM) ----------------
__global__ void __launch_bounds__(256, 2) k_pre(
    const float* __restrict__ h,
    const float* __restrict__ Wh, const float* __restrict__ Win,
    const float* __restrict__ bin)
{
    __shared__ __align__(16) float sWh[128 * 64];
    __shared__ __align__(16) float sWin[128 * 20];
    for (int t = threadIdx.x; t < 128 * 64; t += 256) sWh[t] = Wh[t];
    for (int t = threadIdx.x; t < 128 * 20; t += 256) sWin[t] = Win[t];
    __syncthreads();

    int i = blockIdx.x * 256 + threadIdx.x;
    if (i >= NN) return;
    const float4* h4 = (const float4*)(h + (size_t)i * 64);

    #pragma unroll 1
    for (int g = 0; g < 2; g++) {
        u64 aP[32]; u64 aQ[10];
        #pragma unroll
        for (int q = 0; q < 32; q++) aP[q] = 0ull;
        #pragma unroll
        for (int q = 0; q < 10; q++) aQ[q] = 0ull;
        #pragma unroll 2
        for (int k4 = 0; k4 < 16; k4++) {
            float4 hv = __ldg(&h4[k4]);
            float hvv[4] = {hv.x, hv.y, hv.z, hv.w};
            #pragma unroll
            for (int u = 0; u < 4; u++) {
                int k = g * 64 + k4 * 4 + u;
                u64 a = pk2(hvv[u]);
                const ulonglong2* wr = (const ulonglong2*)&sWh[k * 64];
                #pragma unroll
                for (int t = 0; t < 16; t++) {
                    ulonglong2 ww = wr[t];
                    fma2(aP[2 * t], a, ww.x); fma2(aP[2 * t + 1], a, ww.y);
                }
                const u64* w2 = (const u64*)&sWin[k * 20];
                #pragma unroll
                for (int q = 0; q < 10; q++) fma2(aQ[q], a, w2[q]);
            }
        }
        float* P = (g == 0) ? &g_P1[(size_t)i * 64] : &g_P2[(size_t)i * 64];
        float* Q = (g == 0) ? &g_Q1[(size_t)i * 20] : &g_Q2[(size_t)i * 20];
        float4* P4 = (float4*)P;
        #pragma unroll
        for (int q = 0; q < 16; q++) {
            float2 p0 = upk(aP[2 * q]);
            float2 p1 = upk(aP[2 * q + 1]);
            P4[q] = make_float4(p0.x, p0.y, p1.x, p1.y);
        }
        #pragma unroll
        for (int q = 0; q < 10; q++) {
            float2 p = upk(aQ[q]);
            if (g == 0) {
                Q[2 * q]     = p.x + __ldg(&bin[2 * q]);
                Q[2 * q + 1] = p.y + __ldg(&bin[2 * q + 1]);
            } else {
                Q[2 * q] = p.x; Q[2 * q + 1] = p.y;
            }
        }
    }
}

// ---------------- K1: edge pass 1, low-register two-half pipeline ----------------
__global__ void __launch_bounds__(256, 2) k_edge1(
    const float* __restrict__ xx,
    const float* __restrict__ Wh,  const float* __restrict__ bh,
    const float* __restrict__ Wo,  const float* __restrict__ bo,
    const float* __restrict__ Wa,  const float* __restrict__ ba)
{
    __shared__ __align__(16) float sWr[20 * 64];
    __shared__ __align__(16) float sWl[64];
    __shared__ __align__(16) float sWo[64 * 32];
    __shared__ __align__(16) float sWa[32 * 4];
    __shared__ float sbh[64], sbo[32], sba[4];
    for (int t = threadIdx.x; t < 20 * 64; t += 256) sWr[t] = Wh[128 * 64 + t];
    for (int t = threadIdx.x; t < 64; t += 256)      sWl[t] = Wh[148 * 64 + t];
    for (int t = threadIdx.x; t < 64 * 32; t += 256) sWo[t] = Wo[t];
    for (int t = threadIdx.x; t < 128; t += 256)     sWa[t] = Wa[t];
    if (threadIdx.x < 64) sbh[threadIdx.x] = bh[threadIdx.x];
    if (threadIdx.x < 32) sbo[threadIdx.x] = bo[threadIdx.x];
    if (threadIdx.x < 4)  sba[threadIdx.x] = ba[threadIdx.x];
    __syncthreads();

    int t = blockIdx.x * 256 + threadIdx.x;
    if (t >= EE) return;
    int2 ij = g_sij[t];
    int i = ij.x, j = ij.y;

    float r0 = __ldg(&xx[3 * j])     - __ldg(&xx[3 * i]);
    float r1 = __ldg(&xx[3 * j + 1]) - __ldg(&xx[3 * i + 1]);
    float r2 = __ldg(&xx[3 * j + 2]) - __ldg(&xx[3 * i + 2]);
    float d  = sqrtf(r0 * r0 + r1 * r1 + r2 * r2 + EPSF);
    float inv = 1.f / (d + EPSF);
    float dir0 = r0 * inv, dir1 = r1 * inv, dir2 = r2 * inv;

    float f20[20];
    {
        const float4* q1 = (const float4*)&g_Q1[(size_t)i * 20];
        const float4* q2 = (const float4*)&g_Q2[(size_t)j * 20];
        float ed  = __expf(-d);
        const float mu0  = 0.6065306597126334f;
        const float dmu  = (1.f - mu0) / 19.f;
        const float bb   = 0.1f * (1.f - mu0);
        const float beta = 1.f / (bb * bb);
        #pragma unroll
        for (int q = 0; q < 5; q++) {
            float4 a = __ldg(&q1[q]);
            float4 b = __ldg(&q2[q]);
            float qs[4] = {a.x + b.x, a.y + b.y, a.z + b.z, a.w + b.w};
            #pragma unroll
            for (int u = 0; u < 4; u++) {
                int r = q * 4 + u;
                float tt = ed - (mu0 + r * dmu);
                f20[r] = __expf(-beta * tt * tt) * qs[u];
            }
        }
    }

    u64 ho[16];
    #pragma unroll
    for (int q = 0; q < 16; q++) ho[q] = 0ull;

    const float4* p1b = (const float4*)&g_P1[(size_t)i * 64];
    const float4* p2b = (const float4*)&g_P2[(size_t)j * 64];

    #pragma unroll 1
    for (int half = 0; half < 2; half++) {
        int hc = half * 32;
        u64 a[16];
        #pragma unroll
        for (int q = 0; q < 8; q++) {
            float4 av = __ldg(&p1b[half * 8 + q]);
            float4 bv = __ldg(&p2b[half * 8 + q]);
            a[2 * q]     = pk(av.x + bv.x, av.y + bv.y);
            a[2 * q + 1] = pk(av.z + bv.z, av.w + bv.w);
        }
        #pragma unroll 4
        for (int r = 0; r < 20; r++) {
            u64 fv = pk2(f20[r]);
            const ulonglong2* wr = (const ulonglong2*)&sWr[r * 64 + hc];
            #pragma unroll
            for (int q = 0; q < 8; q++) {
                ulonglong2 ww = wr[q];
                fma2(a[2 * q], fv, ww.x); fma2(a[2 * q + 1], fv, ww.y);
            }
        }
        {
            u64 dv2 = pk2(d);
            const ulonglong2* wr = (const ulonglong2*)&sWl[hc];
            #pragma unroll
            for (int q = 0; q < 8; q++) {
                ulonglong2 ww = wr[q];
                fma2(a[2 * q], dv2, ww.x); fma2(a[2 * q + 1], dv2, ww.y);
            }
        }
        #pragma unroll 4
        for (int q = 0; q < 16; q++) {
            float2 p = upk(a[q]);
            int row = hc + 2 * q;
            float z0 = silu_(p.x + sbh[row]);
            float z1 = silu_(p.y + sbh[row + 1]);
            u64 h0 = pk2(z0), h1 = pk2(z1);
            const ulonglong2* w0 = (const ulonglong2*)&sWo[row * 32];
            const ulonglong2* w1 = (const ulonglong2*)&sWo[(row + 1) * 32];
            #pragma unroll
            for (int c = 0; c < 8; c++) {
                ulonglong2 ww = w0[c];
                fma2(ho[2 * c], h0, ww.x); fma2(ho[2 * c + 1], h0, ww.y);
            }
            #pragma unroll
            for (int c = 0; c < 8; c++) {
                ulonglong2 ww = w1[c];
                fma2(ho[2 * c], h1, ww.x); fma2(ho[2 * c + 1], h1, ww.y);
            }
        }
    }

    float he[32];
    #pragma unroll
    for (int q = 0; q < 16; q++) {
        float2 p = upk(ho[q]);
        he[2 * q]     = p.x + sbo[2 * q];
        he[2 * q + 1] = p.y + sbo[2 * q + 1];
    }

    float4* st = (float4*)&g_hedge[(size_t)t * 32];
    #pragma unroll
    for (int q = 0; q < 8; q++)
        st[q] = make_float4(he[4 * q], he[4 * q + 1], he[4 * q + 2], he[4 * q + 3]);

    float l0 = sba[0], l1 = sba[1], l2 = sba[2], l3 = sba[3];
    const float4* wa4 = (const float4*)sWa;
    #pragma unroll
    for (int c = 0; c < 32; c++) {
        float4 w = wa4[c];
        l0 += he[c] * w.x; l1 += he[c] * w.y; l2 += he[c] * w.z; l3 += he[c] * w.w;
    }
    float e0 = __expf(l0 > 0.f ? l0 : 2.f * (__expf(0.5f * l0) - 1.f));
    float e1 = __expf(l1 > 0.f ? l1 : 2.f * (__expf(0.5f * l1) - 1.f));
    float e2 = __expf(l2 > 0.f ? l2 : 2.f * (__expf(0.5f * l2) - 1.f));
    float e3 = __expf(l3 > 0.f ? l3 : 2.f * (__expf(0.5f * l3) - 1.f));

    ((float4*)g_expl)[t] = make_float4(e0, e1, e2, e3);
    ((float4*)g_dir)[t]  = make_float4(dir0, dir1, dir2, __int_as_float(i));
}

// ---------------- K_agg1: denom + sem, warp-per-node ----------------
__global__ void __launch_bounds__(256) k_agg1() {
    int warp = (blockIdx.x * 256 + threadIdx.x) >> 5;
    int lane = threadIdx.x & 31;
    if (warp >= NN) return;
    int s = g_rowstart[warp];
    int c = g_icnt[warp];

    float a0 = 0.f, a1 = 0.f, a2 = 0.f, a3 = 0.f;
    float d0 = 0.f, d1 = 0.f, d2 = 0.f, d3 = 0.f;
    #pragma unroll 2
    for (int k = 0; k < c; k++) {
        int t = s + k;
        float hev = g_hedge[(size_t)t * 32 + lane];
        float4 ex = ((const float4*)g_expl)[t];
        a0 += ex.x * hev; a1 += ex.y * hev; a2 += ex.z * hev; a3 += ex.w * hev;
        d0 += ex.x; d1 += ex.y; d2 += ex.z; d3 += ex.w;
    }
    float* sb = &g_sem[(size_t)warp * 128];
    sb[lane]      = a0;
    sb[32 + lane] = a1;
    sb[64 + lane] = a2;
    sb[96 + lane] = a3;
    if (lane == 0)
        ((float4*)g_denom)[warp] = make_float4(d0, d1, d2, d3);
}

// ---------------- K2: edge pass 2, TWO edges per thread ----------------
__global__ void __launch_bounds__(256) k_edge2(const float* __restrict__ Wx)
{
    __shared__ __align__(16) float sWx[128 * 32];
    for (int t = threadIdx.x; t < 128 * 32; t += 256) sWx[t] = Wx[t];
    __syncthreads();

    const int HALF = EE / 2;
    int t = blockIdx.x * 256 + threadIdx.x;
    if (t >= HALF) return;
    int tA = t, tB = t + HALF;

    float4 drA = ((const float4*)g_dir)[tA];
    float4 drB = ((const float4*)g_dir)[tB];
    int iA = __float_as_int(drA.w);
    int iB = __float_as_int(drB.w);

    float4 exA = ((const float4*)g_expl)[tA];
    float4 exB = ((const float4*)g_expl)[tB];
    float4 dnA = __ldg((const float4*)&g_denom[iA * 4]);
    float4 dnB = __ldg((const float4*)&g_denom[iB * 4]);
    float atA[4] = { exA.x / (dnA.x + EPSF), exA.y / (dnA.y + EPSF),
                     exA.z / (dnA.z + EPSF), exA.w / (dnA.w + EPSF) };
    float atB[4] = { exB.x / (dnB.x + EPSF), exB.y / (dnB.y + EPSF),
                     exB.z / (dnB.z + EPSF), exB.w / (dnB.w + EPSF) };

    float heA[32], heB[32];
    float4* hbA = (float4*)&g_hedge[(size_t)tA * 32];
    float4* hbB = (float4*)&g_hedge[(size_t)tB * 32];
    #pragma unroll
    for (int q = 0; q < 8; q++) {
        float4 v = hbA[q];
        heA[4 * q] = v.x; heA[4 * q + 1] = v.y; heA[4 * q + 2] = v.z; heA[4 * q + 3] = v.w;
        float4 w = hbB[q];
        heB[4 * q] = w.x; heB[4 * q + 1] = w.y; heB[4 * q + 2] = w.z; heB[4 * q + 3] = w.w;
    }

    u64 mxA[16], mxB[16];
    #pragma unroll
    for (int q = 0; q < 16; q++) { mxA[q] = 0ull; mxB[q] = 0ull; }

    #pragma unroll 4
    for (int k = 0; k < 128; k++) {
        float sA = atA[k >> 5] * heA[k & 31];
        float sB = atB[k >> 5] * heB[k & 31];
        u64 s2A = pk2(sA), s2B = pk2(sB);
        const ulonglong2* wr = (const ulonglong2*)&sWx[k * 32];
        #pragma unroll
        for (int q = 0; q < 8; q++) {
            ulonglong2 ww = wr[q];
            fma2(mxA[2 * q], s2A, ww.x); fma2(mxA[2 * q + 1], s2A, ww.y);
            fma2(mxB[2 * q], s2B, ww.x); fma2(mxB[2 * q + 1], s2B, ww.y);
        }
    }

    #pragma unroll
    for (int q = 0; q < 8; q++) {
        float2 p0 = upk(mxA[2 * q]);
        float2 p1 = upk(mxA[2 * q + 1]);
        hbA[q] = make_float4(tanhf(p0.x), tanhf(p0.y), tanhf(p1.x), tanhf(p1.y));
        float2 q0 = upk(mxB[2 * q]);
        float2 q1 = upk(mxB[2 * q + 1]);
        hbB[q] = make_float4(tanhf(q0.x), tanhf(q0.y), tanhf(q1.x), tanhf(q1.y));
    }
}

// ---------------- K_agg2: comb sums, warp-per-node ----------------
__global__ void __launch_bounds__(256) k_agg2() {
    int warp = (blockIdx.x * 256 + threadIdx.x) >> 5;
    int lane = threadIdx.x & 31;
    if (warp >= NN) return;
    int s = g_rowstart[warp];
    int c = g_icnt[warp];

    float c0 = 0.f, c1 = 0.f, c2 = 0.f;
    #pragma unroll 2
    for (int k = 0; k < c; k++) {
        int t = s + k;
        float mv = g_hedge[(size_t)t * 32 + lane];
        float4 dr = ((const float4*)g_dir)[t];
        c0 += mv * dr.x; c1 += mv * dr.y; c2 += mv * dr.z;
    }
    float* cb = &g_comb[(size_t)warp * 96 + lane * 3];
    cb[0] = c0; cb[1] = c1; cb[2] = c2;
}

// ---------------- K3a: spatial MLP + dv ----------------
__global__ void __launch_bounds__(256) k_spatial(
    const float* __restrict__ Wp1, const float* __restrict__ bp1,
    const float* __restrict__ Wp2, const float* __restrict__ bp2,
    const float* __restrict__ wvm)
{
    __shared__ __align__(16) float sWp1[32 * 64];
    __shared__ __align__(16) float sWp2[64 * 32];
    __shared__ float sbp1[64], sbp2[32], swv[32];
    for (int t = threadIdx.x; t < 2048; t += 256) sWp1[t] = Wp1[t];
    for (int t = threadIdx.x; t < 2048; t += 256) sWp2[t] = Wp2[t];
    if (threadIdx.x < 64) sbp1[threadIdx.x] = bp1[threadIdx.x];
    if (threadIdx.x < 32) sbp2[threadIdx.x] = bp2[threadIdx.x];
    if (threadIdx.x < 32) swv[threadIdx.x] = wvm[threadIdx.x];
    __syncthreads();

    int i = blockIdx.x * 256 + threadIdx.x;
    if (i >= NN) return;

    float invc = 1.f / fmaxf(g_cnt[i], 1.f);
    float n2[32];
    float dv0 = 0.f, dv1 = 0.f, dv2 = 0.f;
    {
        float val[96];
        const float4* cb = (const float4*)&g_comb[(size_t)i * 96];
        #pragma unroll
        for (int q = 0; q < 24; q++) {
            float4 v = __ldg(&cb[q]);
            val[4 * q] = v.x; val[4 * q + 1] = v.y; val[4 * q + 2] = v.z; val[4 * q + 3] = v.w;
        }
        #pragma unroll
        for (int c = 0; c < 32; c++) {
            float ax = val[3 * c] * invc, ay = val[3 * c + 1] * invc, az = val[3 * c + 2] * invc;
            n2[c] = ax * ax + ay * ay + az * az;
            float w = swv[c];
            dv0 += ax * w; dv1 += ay * w; dv2 += az * w;
        }
    }

    u64 s2acc[16];
    #pragma unroll
    for (int q = 0; q < 16; q++) s2acc[q] = 0ull;

    #pragma unroll 1
    for (int half = 0; half < 2; half++) {
        u64 acc[16];
        #pragma unroll
        for (int q = 0; q < 16; q++) acc[q] = 0ull;
        #pragma unroll 4
        for (int k = 0; k < 32; k++) {
            u64 nv = pk2(n2[k]);
            const ulonglong2* w = (const ulonglong2*)&sWp1[k * 64 + half * 32];
            #pragma unroll
            for (int q = 0; q < 8; q++) {
                ulonglong2 ww = w[q];
                fma2(acc[2 * q], nv, ww.x); fma2(acc[2 * q + 1], nv, ww.y);
            }
        }
        #pragma unroll 2
        for (int q = 0; q < 16; q++) {
            float2 p = upk(acc[q]);
            int row = half * 32 + 2 * q;
            float z0 = silu_(p.x + sbp1[row]);
            float z1 = silu_(p.y + sbp1[row + 1]);
            u64 a0 = pk2(z0), a1 = pk2(z1);
            const ulonglong2* w0 = (const ulonglong2*)&sWp2[row * 32];
            const ulonglong2* w1 = (const ulonglong2*)&sWp2[(row + 1) * 32];
            #pragma unroll
            for (int c = 0; c < 8; c++) {
                ulonglong2 ww = w0[c];
                fma2(s2acc[2 * c], a0, ww.x); fma2(s2acc[2 * c + 1], a0, ww.y);
            }
            #pragma unroll
            for (int c = 0; c < 8; c++) {
                ulonglong2 ww = w1[c];
                fma2(s2acc[2 * c], a1, ww.x); fma2(s2acc[2 * c + 1], a1, ww.y);
            }
        }
    }
    float4* sp4 = (float4*)&g_spa[(size_t)i * 32];
    #pragma unroll
    for (int q = 0; q < 8; q++) {
        float2 p0 = upk(s2acc[2 * q]);
        float2 p1 = upk(s2acc[2 * q + 1]);
        sp4[q] = make_float4(silu_(p0.x + sbp2[4 * q]),     silu_(p0.y + sbp2[4 * q + 1]),
                             silu_(p1.x + sbp2[4 * q + 2]), silu_(p1.y + sbp2[4 * q + 3]));
    }
    ((float4*)g_dv)[i] = make_float4(dv0, dv1, dv2, 0.f);
}

// ---------------- K3b-1: node MLP layer1, HALF of the output columns ----------------
// smem = W1[:, half*64 .. +64] = 57,344 B -> genuinely 2 blocks/SM (115KB), 16 warps.
__global__ void __launch_bounds__(256, 2) k_node1h(
    const float* __restrict__ h,
    const float* __restrict__ W1, const float* __restrict__ b1, int half)
{
    extern __shared__ __align__(16) float sw[];
    float* sW = sw;            // [224][64]
    float* sb = sw + 224 * 64; // 64

    {
        int cbase = half * 64;
        for (int t = threadIdx.x; t < 224 * 64; t += 256) {
            int row = t >> 6, col = t & 63;
            sW[t] = W1[row * 128 + cbase + col];
        }
        if (threadIdx.x < 64) sb[threadIdx.x] = b1[half * 64 + threadIdx.x];
    }
    __syncthreads();

    int i = blockIdx.x * 256 + threadIdx.x;
    if (i >= NN) return;

    float4 dn = __ldg((const float4*)&g_denom[i * 4]);
    float inv4[4] = { 1.f / (dn.x + EPSF), 1.f / (dn.y + EPSF),
                      1.f / (dn.z + EPSF), 1.f / (dn.w + EPSF) };

    const float4* hs = (const float4*)(h + (size_t)i * 64);
    const float4* ss = (const float4*)&g_sem[(size_t)i * 128];
    const float4* ps = (const float4*)&g_spa[(size_t)i * 32];
    float4* zo = (float4*)&g_z[(size_t)i * 128 + half * 64];

    #pragma unroll 1
    for (int cq = 0; cq < 2; cq++) {          // 32-column groups within the half
        int co = cq * 32;
        u64 acc[16];
        #pragma unroll
        for (int q = 0; q < 16; q++) acc[q] = 0ull;

        {
            float4 cur = __ldg(&hs[0]);
            #pragma unroll 1
            for (int k4 = 0; k4 < 16; k4++) {
                float4 nxt = (k4 < 15) ? __ldg(&hs[k4 + 1]) : make_float4(0.f, 0.f, 0.f, 0.f);
                float av[4] = {cur.x, cur.y, cur.z, cur.w};
                #pragma unroll
                for (int u = 0; u < 4; u++) {
                    u64 a = pk2(av[u]);
                    const ulonglong2* w = (const ulonglong2*)&sW[(k4 * 4 + u) * 64 + co];
                    #pragma unroll
                    for (int q = 0; q < 8; q++) {
                        ulonglong2 ww = w[q];
                        fma2(acc[2 * q], a, ww.x); fma2(acc[2 * q + 1], a, ww.y);
                    }
                }
                cur = nxt;
            }
        }
        {
            float4 cur = __ldg(&ss[0]);
            #pragma unroll 1
            for (int k4 = 0; k4 < 32; k4++) {
                float4 nxt = (k4 < 31) ? __ldg(&ss[k4 + 1]) : make_float4(0.f, 0.f, 0.f, 0.f);
                float sc = inv4[k4 >> 3];
                float av[4] = {cur.x * sc, cur.y * sc, cur.z * sc, cur.w * sc};
                #pragma unroll
                for (int u = 0; u < 4; u++) {
                    u64 a = pk2(av[u]);
                    const ulonglong2* w = (const ulonglong2*)&sW[(64 + k4 * 4 + u) * 64 + co];
                    #pragma unroll
                    for (int q = 0; q < 8; q++) {
                        ulonglong2 ww = w[q];
                        fma2(acc[2 * q], a, ww.x); fma2(acc[2 * q + 1], a, ww.y);
                    }
                }
                cur = nxt;
            }
        }
        {
            float4 cur = __ldg(&ps[0]);
            #pragma unroll 1
            for (int k4 = 0; k4 < 8; k4++) {
                float4 nxt = (k4 < 7) ? __ldg(&ps[k4 + 1]) : make_float4(0.f, 0.f, 0.f, 0.f);
                float av[4] = {cur.x, cur.y, cur.z, cur.w};
                #pragma unroll
                for (int u = 0; u < 4; u++) {
                    u64 a = pk2(av[u]);
                    const ulonglong2* w = (const ulonglong2*)&sW[(192 + k4 * 4 + u) * 64 + co];
                    #pragma unroll
                    for (int q = 0; q < 8; q++) {
                        ulonglong2 ww = w[q];
                        fma2(acc[2 * q], a, ww.x); fma2(acc[2 * q + 1], a, ww.y);
                    }
                }
                cur = nxt;
            }
        }
        // silu + store this 32-col group
        #pragma unroll
        for (int q = 0; q < 8; q++) {
            float2 p0 = upk(acc[2 * q]);
            float2 p1 = upk(acc[2 * q + 1]);
            int row = co + 4 * q;
            zo[(co >> 2) + q] = make_float4(
                silu_(p0.x + sb[row]),     silu_(p0.y + sb[row + 1]),
                silu_(p1.x + sb[row + 2]), silu_(p1.y + sb[row + 3]));
        }
    }
}

// ---------------- K3b-2: node MLP layer2 + gate + outputs ----------------
__global__ void __launch_bounds__(256) k_node2(
    const float* __restrict__ h, const float* __restrict__ xx, const float* __restrict__ vv,
    const float* __restrict__ W2,  const float* __restrict__ b2,
    const float* __restrict__ Wv1, const float* __restrict__ bv1,
    const float* __restrict__ Wv2,
    float* __restrict__ out)
{
    __shared__ __align__(16) float sW2[128 * 64];   // 32 KB
    __shared__ __align__(16) float sWv1[64 * 32];   // 8 KB
    __shared__ float sb2[64], sbv1[32], sWv2[32];
    for (int t = threadIdx.x; t < 8192; t += 256) sW2[t] = W2[t];
    for (int t = threadIdx.x; t < 2048; t += 256) sWv1[t] = Wv1[t];
    if (threadIdx.x < 64) sb2[threadIdx.x] = b2[threadIdx.x];
    if (threadIdx.x < 32) sbv1[threadIdx.x] = bv1[threadIdx.x];
    if (threadIdx.x < 32) sWv2[threadIdx.x] = Wv2[threadIdx.x];
    __syncthreads();

    int i = blockIdx.x * 256 + threadIdx.x;
    if (i >= NN) return;

    const float4* zi = (const float4*)&g_z[(size_t)i * 128];

    u64 acc2[32];
    #pragma unroll
    for (int q = 0; q < 32; q++) acc2[q] = 0ull;

    {
        float4 cur = __ldg(&zi[0]);
        #pragma unroll 1
        for (int k4 = 0; k4 < 32; k4++) {
            float4 nxt = (k4 < 31) ? __ldg(&zi[k4 + 1]) : make_float4(0.f, 0.f, 0.f, 0.f);
            float av[4] = {cur.x, cur.y, cur.z, cur.w};
            #pragma unroll
            for (int u = 0; u < 4; u++) {
                u64 a = pk2(av[u]);
                const ulonglong2* w = (const ulonglong2*)&sW2[(k4 * 4 + u) * 64];
                #pragma unroll
                for (int q = 0; q < 16; q++) {
                    ulonglong2 ww = w[q];
                    fma2(acc2[2 * q], a, ww.x); fma2(acc2[2 * q + 1], a, ww.y);
                }
            }
            cur = nxt;
        }
    }

    const float* hr = h + (size_t)i * 64;
    float2* outh = (float2*)&out[(size_t)i * 64];
    u64 ga[16];
    #pragma unroll
    for (int q = 0; q < 16; q++) ga[q] = 0ull;

    #pragma unroll 1
    for (int q = 0; q < 32; q++) {
        float2 p = upk(acc2[q]);
        float hu0 = __ldg(&hr[2 * q])     + silu_(p.x + sb2[2 * q]);
        float hu1 = __ldg(&hr[2 * q + 1]) + silu_(p.y + sb2[2 * q + 1]);
        outh[q] = make_float2(hu0, hu1);
        u64 a0 = pk2(hu0), a1 = pk2(hu1);
        const ulonglong2* w0 = (const ulonglong2*)&sWv1[(2 * q) * 32];
        const ulonglong2* w1 = (const ulonglong2*)&sWv1[(2 * q + 1) * 32];
        #pragma unroll
        for (int c = 0; c < 8; c++) {
            ulonglong2 ww = w0[c];
            fma2(ga[2 * c], a0, ww.x); fma2(ga[2 * c + 1], a0, ww.y);
        }
        #pragma unroll
        for (int c = 0; c < 8; c++) {
            ulonglong2 ww = w1[c];
            fma2(ga[2 * c], a1, ww.x); fma2(ga[2 * c + 1], a1, ww.y);
        }
    }

    float g = 0.f;
    #pragma unroll
    for (int q = 0; q < 16; q++) {
        float2 p = upk(ga[q]);
        g += silu_(p.x + sbv1[2 * q])     * sWv2[2 * q];
        g += silu_(p.y + sbv1[2 * q + 1]) * sWv2[2 * q + 1];
    }
    float gate = 2.f * (1.f / (1.f + __expf(-g)));

    float4 dv = __ldg((const float4*)&g_dv[i * 4]);
    float vx = gate * vv[3 * i]     + dv.x;
    float vy = gate * vv[3 * i + 1] + dv.y;
    float vz = gate * vv[3 * i + 2] + dv.z;
    float* outx = out + (size_t)NN * 64;
    float* outv = outx + (size_t)NN * 3;
    outx[3 * i]     = xx[3 * i]     + vx;
    outx[3 * i + 1] = xx[3 * i + 1] + vy;
    outx[3 * i + 2] = xx[3 * i + 2] + vz;
    outv[3 * i] = vx;  outv[3 * i + 1] = vy;  outv[3 * i + 2] = vz;
}

// ---------------- launch ----------------
extern "C" void kernel_launch(void* const* d_in, const int* in_sizes, int n_in,
                              void* d_out, int out_size) {
    const float* h   = (const float*)d_in[0];
    const float* x   = (const float*)d_in[1];
    const float* v   = (const float*)d_in[2];
    const int*   ii  = (const int*)d_in[3];
    const int*   jj  = (const int*)d_in[4];
    const float* Win = (const float*)d_in[5];
    const float* bin = (const float*)d_in[6];
    const float* Wh  = (const float*)d_in[7];
    const float* bh  = (const float*)d_in[8];
    const float* Wo  = (const float*)d_in[9];
    const float* bo  = (const float*)d_in[10];
    const float* Wa  = (const float*)d_in[11];
    const float* ba  = (const float*)d_in[12];
    const float* Wx  = (const float*)d_in[13];
    const float* W1  = (const float*)d_in[14];
    const float* b1  = (const float*)d_in[15];
    const float* W2  = (const float*)d_in[16];
    const float* b2  = (const float*)d_in[17];
    const float* Wp1 = (const float*)d_in[18];
    const float* bp1 = (const float*)d_in[19];
    const float* Wp2 = (const float*)d_in[20];
    const float* bp2 = (const float*)d_in[21];
    const float* Wv1 = (const float*)d_in[22];
    const float* bv1 = (const float*)d_in[23];
    const float* Wv2 = (const float*)d_in[24];
    const float* wvm = (const float*)d_in[25];
    float* out = (float*)d_out;

    const int N1_SMEM = (224 * 64 + 64) * 4;   // 57,600 B
    cudaFuncSetAttribute(k_node1h, cudaFuncAttributeMaxDynamicSharedMemorySize, N1_SMEM);

    const int NSCAN = (NN + 255) / 256;   // 196

    k_zero<<<(NN + 256 + 255) / 256, 256>>>();
    k_count<<<(EE + 255) / 256, 256>>>(ii);
    k_pre<<<(NN + 255) / 256, 256>>>(h, Wh, Win, bin);
    k_scan_a<<<NSCAN, 256>>>();
    k_scan_b<<<1, 256>>>(NSCAN);
    k_scan_c<<<NSCAN, 256>>>();
    k_scatter<<<(EE + 255) / 256, 256>>>(ii, jj);
    k_edge1<<<(EE + 255) / 256, 256>>>(x, Wh, bh, Wo, bo, Wa, ba);
    k_agg1<<<(NN * 32 + 255) / 256, 256>>>();
    k_edge2<<<(EE / 2 + 255) / 256, 256>>>(Wx);
    k_agg2<<<(NN * 32 + 255) / 256, 256>>>();
    k_spatial<<<(NN + 255) / 256, 256>>>(Wp1, bp1, Wp2, bp2, wvm);
    k_node1h<<<NSCAN, 256, N1_SMEM>>>(h, W1, b1, 0);
    k_node1h<<<NSCAN, 256, N1_SMEM>>>(h, W1, b1, 1);
    k_node2<<<NSCAN, 256>>>(h, x, v, W2, b2, Wv1, bv1, Wv2, out);
}

// round 13
// speedup vs baseline: 1.1033x; 1.1033x over previous
#include <cuda_runtime.h>

#define NN 50000
#define EE 500000
#define EPSF 1e-8f

typedef unsigned long long u64;

// ---------------- scratch (device globals) ----------------
__device__ __align__(16) float g_hedge[EE * 32];   // he (pass1) then m (pass2)
__device__ __align__(16) float g_expl[EE * 4];
__device__ __align__(16) float g_dir[EE * 4];
__device__ __align__(16) float g_denom[NN * 4];
__device__ __align__(16) float g_cnt[NN];
__device__ __align__(16) float g_sem[NN * 128];
__device__ __align__(16) float g_comb[NN * 96];
__device__ __align__(16) float g_P1[NN * 64];
__device__ __align__(16) float g_P2[NN * 64];
__device__ __align__(16) float g_Q1[NN * 20];
__device__ __align__(16) float g_Q2[NN * 20];
__device__ __align__(16) float g_spa[NN * 32];
__device__ __align__(16) float g_dv[NN * 4];
// sorting infra
__device__ __align__(16) int g_icnt[NN + 256];
__device__ __align__(16) int g_rowstart[NN];
__device__ __align__(16) int g_woff[NN];
__device__ __align__(16) int2 g_sij[EE];
__device__ __align__(16) int g_bsum[256];
__device__ __align__(16) int g_boff[256];

// ---------------- helpers ----------------
__device__ __forceinline__ u64 pk2(float v) {
    u64 r; asm("mov.b64 %0,{%1,%1};" : "=l"(r) : "f"(v)); return r;
}
__device__ __forceinline__ u64 pk(float a, float b) {
    u64 r; asm("mov.b64 %0,{%1,%2};" : "=l"(r) : "f"(a), "f"(b)); return r;
}
__device__ __forceinline__ void fma2(u64 &d, u64 a, u64 b) {
    asm("fma.rn.f32x2 %0,%1,%2,%0;" : "+l"(d) : "l"(a), "l"(b));
}
__device__ __forceinline__ float2 upk(u64 v) {
    float2 f; asm("mov.b64 {%0,%1},%2;" : "=f"(f.x), "=f"(f.y) : "l"(v)); return f;
}
__device__ __forceinline__ float silu_(float z) { return z * (1.f / (1.f + __expf(-z))); }

// ---------------- K0: zero icnt ----------------
__global__ void k_zero() {
    int t = blockIdx.x * blockDim.x + threadIdx.x;
    if (t < NN + 256) g_icnt[t] = 0;
}

// ---------------- sort: histogram ----------------
__global__ void k_count(const int* __restrict__ idx_i) {
    int e = blockIdx.x * blockDim.x + threadIdx.x;
    if (e < EE) atomicAdd(&g_icnt[idx_i[e]], 1);
}

// ---------------- sort: block sums ----------------
__global__ void __launch_bounds__(256) k_scan_a() {
    __shared__ int s[256];
    int n = blockIdx.x * 256 + threadIdx.x;
    int v = (n < NN) ? g_icnt[n] : 0;
    s[threadIdx.x] = v;
    __syncthreads();
    #pragma unroll
    for (int off = 128; off > 0; off >>= 1) {
        if (threadIdx.x < off) s[threadIdx.x] += s[threadIdx.x + off];
        __syncthreads();
    }
    if (threadIdx.x == 0) g_bsum[blockIdx.x] = s[0];
}

// ---------------- sort: scan of block sums ----------------
__global__ void __launch_bounds__(256) k_scan_b(int nblocks) {
    __shared__ int s[256];
    int t = threadIdx.x;
    int v = (t < nblocks) ? g_bsum[t] : 0;
    s[t] = v;
    __syncthreads();
    #pragma unroll
    for (int off = 1; off < 256; off <<= 1) {
        int u = (t >= off) ? s[t - off] : 0;
        __syncthreads();
        s[t] += u;
        __syncthreads();
    }
    g_boff[t] = s[t] - v;   // exclusive
}

// ---------------- sort: per-block scan + offsets ----------------
__global__ void __launch_bounds__(256) k_scan_c() {
    __shared__ int s[256];
    int n = blockIdx.x * 256 + threadIdx.x;
    int c = (n < NN) ? g_icnt[n] : 0;
    int t = threadIdx.x;
    s[t] = c;
    __syncthreads();
    #pragma unroll
    for (int off = 1; off < 256; off <<= 1) {
        int u = (t >= off) ? s[t - off] : 0;
        __syncthreads();
        s[t] += u;
        __syncthreads();
    }
    if (n < NN) {
        int rs = g_boff[blockIdx.x] + s[t] - c;
        g_rowstart[n] = rs;
        g_woff[n] = rs;
        g_cnt[n] = (float)c;
    }
}

// ---------------- sort: scatter sorted (i,j) ----------------
__global__ void k_scatter(const int* __restrict__ idx_i, const int* __restrict__ idx_j) {
    int e = blockIdx.x * blockDim.x + threadIdx.x;
    if (e >= EE) return;
    int i = idx_i[e];
    int pos = atomicAdd(&g_woff[i], 1);
    g_sij[pos] = make_int2(i, idx_j[e]);
}

// ---------------- K_pre: per-node projections (2 blocks/SM) ----------------
__global__ void __launch_bounds__(256, 2) k_pre(
    const float* __restrict__ h,
    const float* __restrict__ Wh, const float* __restrict__ Win,
    const float* __restrict__ bin)
{
    __shared__ __align__(16) float sWh[128 * 64];
    __shared__ __align__(16) float sWin[128 * 20];
    for (int t = threadIdx.x; t < 128 * 64; t += 256) sWh[t] = Wh[t];
    for (int t = threadIdx.x; t < 128 * 20; t += 256) sWin[t] = Win[t];
    __syncthreads();

    int i = blockIdx.x * 256 + threadIdx.x;
    if (i >= NN) return;
    const float4* h4 = (const float4*)(h + (size_t)i * 64);

    #pragma unroll 1
    for (int g = 0; g < 2; g++) {
        u64 aP[32]; u64 aQ[10];
        #pragma unroll
        for (int q = 0; q < 32; q++) aP[q] = 0ull;
        #pragma unroll
        for (int q = 0; q < 10; q++) aQ[q] = 0ull;
        #pragma unroll 2
        for (int k4 = 0; k4 < 16; k4++) {
            float4 hv = __ldg(&h4[k4]);
            float hvv[4] = {hv.x, hv.y, hv.z, hv.w};
            #pragma unroll
            for (int u = 0; u < 4; u++) {
                int k = g * 64 + k4 * 4 + u;
                u64 a = pk2(hvv[u]);
                const ulonglong2* wr = (const ulonglong2*)&sWh[k * 64];
                #pragma unroll
                for (int t = 0; t < 16; t++) {
                    ulonglong2 ww = wr[t];
                    fma2(aP[2 * t], a, ww.x); fma2(aP[2 * t + 1], a, ww.y);
                }
                const u64* w2 = (const u64*)&sWin[k * 20];
                #pragma unroll
                for (int q = 0; q < 10; q++) fma2(aQ[q], a, w2[q]);
            }
        }
        float* P = (g == 0) ? &g_P1[(size_t)i * 64] : &g_P2[(size_t)i * 64];
        float* Q = (g == 0) ? &g_Q1[(size_t)i * 20] : &g_Q2[(size_t)i * 20];
        float4* P4 = (float4*)P;
        #pragma unroll
        for (int q = 0; q < 16; q++) {
            float2 p0 = upk(aP[2 * q]);
            float2 p1 = upk(aP[2 * q + 1]);
            P4[q] = make_float4(p0.x, p0.y, p1.x, p1.y);
        }
        #pragma unroll
        for (int q = 0; q < 10; q++) {
            float2 p = upk(aQ[q]);
            if (g == 0) {
                Q[2 * q]     = p.x + __ldg(&bin[2 * q]);
                Q[2 * q + 1] = p.y + __ldg(&bin[2 * q + 1]);
            } else {
                Q[2 * q] = p.x; Q[2 * q + 1] = p.y;
            }
        }
    }
}

// ---------------- K1: edge pass 1, low-register two-half pipeline ----------------
__global__ void __launch_bounds__(256, 2) k_edge1(
    const float* __restrict__ xx,
    const float* __restrict__ Wh,  const float* __restrict__ bh,
    const float* __restrict__ Wo,  const float* __restrict__ bo,
    const float* __restrict__ Wa,  const float* __restrict__ ba)
{
    __shared__ __align__(16) float sWr[20 * 64];
    __shared__ __align__(16) float sWl[64];
    __shared__ __align__(16) float sWo[64 * 32];
    __shared__ __align__(16) float sWa[32 * 4];
    __shared__ float sbh[64], sbo[32], sba[4];
    for (int t = threadIdx.x; t < 20 * 64; t += 256) sWr[t] = Wh[128 * 64 + t];
    for (int t = threadIdx.x; t < 64; t += 256)      sWl[t] = Wh[148 * 64 + t];
    for (int t = threadIdx.x; t < 64 * 32; t += 256) sWo[t] = Wo[t];
    for (int t = threadIdx.x; t < 128; t += 256)     sWa[t] = Wa[t];
    if (threadIdx.x < 64) sbh[threadIdx.x] = bh[threadIdx.x];
    if (threadIdx.x < 32) sbo[threadIdx.x] = bo[threadIdx.x];
    if (threadIdx.x < 4)  sba[threadIdx.x] = ba[threadIdx.x];
    __syncthreads();

    int t = blockIdx.x * 256 + threadIdx.x;
    if (t >= EE) return;
    int2 ij = g_sij[t];
    int i = ij.x, j = ij.y;

    float r0 = __ldg(&xx[3 * j])     - __ldg(&xx[3 * i]);
    float r1 = __ldg(&xx[3 * j + 1]) - __ldg(&xx[3 * i + 1]);
    float r2 = __ldg(&xx[3 * j + 2]) - __ldg(&xx[3 * i + 2]);
    float d  = sqrtf(r0 * r0 + r1 * r1 + r2 * r2 + EPSF);
    float inv = 1.f / (d + EPSF);
    float dir0 = r0 * inv, dir1 = r1 * inv, dir2 = r2 * inv;

    float f20[20];
    {
        const float4* q1 = (const float4*)&g_Q1[(size_t)i * 20];
        const float4* q2 = (const float4*)&g_Q2[(size_t)j * 20];
        float ed  = __expf(-d);
        const float mu0  = 0.6065306597126334f;
        const float dmu  = (1.f - mu0) / 19.f;
        const float bb   = 0.1f * (1.f - mu0);
        const float beta = 1.f / (bb * bb);
        #pragma unroll
        for (int q = 0; q < 5; q++) {
            float4 a = __ldg(&q1[q]);
            float4 b = __ldg(&q2[q]);
            float qs[4] = {a.x + b.x, a.y + b.y, a.z + b.z, a.w + b.w};
            #pragma unroll
            for (int u = 0; u < 4; u++) {
                int r = q * 4 + u;
                float tt = ed - (mu0 + r * dmu);
                f20[r] = __expf(-beta * tt * tt) * qs[u];
            }
        }
    }

    u64 ho[16];
    #pragma unroll
    for (int q = 0; q < 16; q++) ho[q] = 0ull;

    const float4* p1b = (const float4*)&g_P1[(size_t)i * 64];
    const float4* p2b = (const float4*)&g_P2[(size_t)j * 64];

    #pragma unroll 1
    for (int half = 0; half < 2; half++) {
        int hc = half * 32;
        u64 a[16];
        #pragma unroll
        for (int q = 0; q < 8; q++) {
            float4 av = __ldg(&p1b[half * 8 + q]);
            float4 bv = __ldg(&p2b[half * 8 + q]);
            a[2 * q]     = pk(av.x + bv.x, av.y + bv.y);
            a[2 * q + 1] = pk(av.z + bv.z, av.w + bv.w);
        }
        #pragma unroll 4
        for (int r = 0; r < 20; r++) {
            u64 fv = pk2(f20[r]);
            const ulonglong2* wr = (const ulonglong2*)&sWr[r * 64 + hc];
            #pragma unroll
            for (int q = 0; q < 8; q++) {
                ulonglong2 ww = wr[q];
                fma2(a[2 * q], fv, ww.x); fma2(a[2 * q + 1], fv, ww.y);
            }
        }
        {
            u64 dv2 = pk2(d);
            const ulonglong2* wr = (const ulonglong2*)&sWl[hc];
            #pragma unroll
            for (int q = 0; q < 8; q++) {
                ulonglong2 ww = wr[q];
                fma2(a[2 * q], dv2, ww.x); fma2(a[2 * q + 1], dv2, ww.y);
            }
        }
        #pragma unroll 4
        for (int q = 0; q < 16; q++) {
            float2 p = upk(a[q]);
            int row = hc + 2 * q;
            float z0 = silu_(p.x + sbh[row]);
            float z1 = silu_(p.y + sbh[row + 1]);
            u64 h0 = pk2(z0), h1 = pk2(z1);
            const ulonglong2* w0 = (const ulonglong2*)&sWo[row * 32];
            const ulonglong2* w1 = (const ulonglong2*)&sWo[(row + 1) * 32];
            #pragma unroll
            for (int c = 0; c < 8; c++) {
                ulonglong2 ww = w0[c];
                fma2(ho[2 * c], h0, ww.x); fma2(ho[2 * c + 1], h0, ww.y);
            }
            #pragma unroll
            for (int c = 0; c < 8; c++) {
                ulonglong2 ww = w1[c];
                fma2(ho[2 * c], h1, ww.x); fma2(ho[2 * c + 1], h1, ww.y);
            }
        }
    }

    float he[32];
    #pragma unroll
    for (int q = 0; q < 16; q++) {
        float2 p = upk(ho[q]);
        he[2 * q]     = p.x + sbo[2 * q];
        he[2 * q + 1] = p.y + sbo[2 * q + 1];
    }

    float4* st = (float4*)&g_hedge[(size_t)t * 32];
    #pragma unroll
    for (int q = 0; q < 8; q++)
        st[q] = make_float4(he[4 * q], he[4 * q + 1], he[4 * q + 2], he[4 * q + 3]);

    float l0 = sba[0], l1 = sba[1], l2 = sba[2], l3 = sba[3];
    const float4* wa4 = (const float4*)sWa;
    #pragma unroll
    for (int c = 0; c < 32; c++) {
        float4 w = wa4[c];
        l0 += he[c] * w.x; l1 += he[c] * w.y; l2 += he[c] * w.z; l3 += he[c] * w.w;
    }
    float e0 = __expf(l0 > 0.f ? l0 : 2.f * (__expf(0.5f * l0) - 1.f));
    float e1 = __expf(l1 > 0.f ? l1 : 2.f * (__expf(0.5f * l1) - 1.f));
    float e2 = __expf(l2 > 0.f ? l2 : 2.f * (__expf(0.5f * l2) - 1.f));
    float e3 = __expf(l3 > 0.f ? l3 : 2.f * (__expf(0.5f * l3) - 1.f));

    ((float4*)g_expl)[t] = make_float4(e0, e1, e2, e3);
    ((float4*)g_dir)[t]  = make_float4(dir0, dir1, dir2, __int_as_float(i));
}

// ---------------- K_agg1: denom + sem, warp-per-node ----------------
__global__ void __launch_bounds__(256) k_agg1() {
    int warp = (blockIdx.x * 256 + threadIdx.x) >> 5;
    int lane = threadIdx.x & 31;
    if (warp >= NN) return;
    int s = g_rowstart[warp];
    int c = g_icnt[warp];

    float a0 = 0.f, a1 = 0.f, a2 = 0.f, a3 = 0.f;
    float d0 = 0.f, d1 = 0.f, d2 = 0.f, d3 = 0.f;
    #pragma unroll 4
    for (int k = 0; k < c; k++) {
        int t = s + k;
        float hev = g_hedge[(size_t)t * 32 + lane];
        float4 ex = ((const float4*)g_expl)[t];
        a0 += ex.x * hev; a1 += ex.y * hev; a2 += ex.z * hev; a3 += ex.w * hev;
        d0 += ex.x; d1 += ex.y; d2 += ex.z; d3 += ex.w;
    }
    float* sb = &g_sem[(size_t)warp * 128];
    sb[lane]      = a0;
    sb[32 + lane] = a1;
    sb[64 + lane] = a2;
    sb[96 + lane] = a3;
    if (lane == 0)
        ((float4*)g_denom)[warp] = make_float4(d0, d1, d2, d3);
}

// ---------------- K2: edge pass 2, TWO edges per thread ----------------
__global__ void __launch_bounds__(256) k_edge2(const float* __restrict__ Wx)
{
    __shared__ __align__(16) float sWx[128 * 32];
    for (int t = threadIdx.x; t < 128 * 32; t += 256) sWx[t] = Wx[t];
    __syncthreads();

    const int HALF = EE / 2;
    int t = blockIdx.x * 256 + threadIdx.x;
    if (t >= HALF) return;
    int tA = t, tB = t + HALF;

    float4 drA = ((const float4*)g_dir)[tA];
    float4 drB = ((const float4*)g_dir)[tB];
    int iA = __float_as_int(drA.w);
    int iB = __float_as_int(drB.w);

    float4 exA = ((const float4*)g_expl)[tA];
    float4 exB = ((const float4*)g_expl)[tB];
    float4 dnA = __ldg((const float4*)&g_denom[iA * 4]);
    float4 dnB = __ldg((const float4*)&g_denom[iB * 4]);
    float atA[4] = { exA.x / (dnA.x + EPSF), exA.y / (dnA.y + EPSF),
                     exA.z / (dnA.z + EPSF), exA.w / (dnA.w + EPSF) };
    float atB[4] = { exB.x / (dnB.x + EPSF), exB.y / (dnB.y + EPSF),
                     exB.z / (dnB.z + EPSF), exB.w / (dnB.w + EPSF) };

    float heA[32], heB[32];
    float4* hbA = (float4*)&g_hedge[(size_t)tA * 32];
    float4* hbB = (float4*)&g_hedge[(size_t)tB * 32];
    #pragma unroll
    for (int q = 0; q < 8; q++) {
        float4 v = hbA[q];
        heA[4 * q] = v.x; heA[4 * q + 1] = v.y; heA[4 * q + 2] = v.z; heA[4 * q + 3] = v.w;
        float4 w = hbB[q];
        heB[4 * q] = w.x; heB[4 * q + 1] = w.y; heB[4 * q + 2] = w.z; heB[4 * q + 3] = w.w;
    }

    u64 mxA[16], mxB[16];
    #pragma unroll
    for (int q = 0; q < 16; q++) { mxA[q] = 0ull; mxB[q] = 0ull; }

    #pragma unroll 4
    for (int k = 0; k < 128; k++) {
        float sA = atA[k >> 5] * heA[k & 31];
        float sB = atB[k >> 5] * heB[k & 31];
        u64 s2A = pk2(sA), s2B = pk2(sB);
        const ulonglong2* wr = (const ulonglong2*)&sWx[k * 32];
        #pragma unroll
        for (int q = 0; q < 8; q++) {
            ulonglong2 ww = wr[q];
            fma2(mxA[2 * q], s2A, ww.x); fma2(mxA[2 * q + 1], s2A, ww.y);
            fma2(mxB[2 * q], s2B, ww.x); fma2(mxB[2 * q + 1], s2B, ww.y);
        }
    }

    #pragma unroll
    for (int q = 0; q < 8; q++) {
        float2 p0 = upk(mxA[2 * q]);
        float2 p1 = upk(mxA[2 * q + 1]);
        hbA[q] = make_float4(tanhf(p0.x), tanhf(p0.y), tanhf(p1.x), tanhf(p1.y));
        float2 q0 = upk(mxB[2 * q]);
        float2 q1 = upk(mxB[2 * q + 1]);
        hbB[q] = make_float4(tanhf(q0.x), tanhf(q0.y), tanhf(q1.x), tanhf(q1.y));
    }
}

// ---------------- K_agg2: comb sums, warp-per-node ----------------
__global__ void __launch_bounds__(256) k_agg2() {
    int warp = (blockIdx.x * 256 + threadIdx.x) >> 5;
    int lane = threadIdx.x & 31;
    if (warp >= NN) return;
    int s = g_rowstart[warp];
    int c = g_icnt[warp];

    float c0 = 0.f, c1 = 0.f, c2 = 0.f;
    #pragma unroll 4
    for (int k = 0; k < c; k++) {
        int t = s + k;
        float mv = g_hedge[(size_t)t * 32 + lane];
        float4 dr = ((const float4*)g_dir)[t];
        c0 += mv * dr.x; c1 += mv * dr.y; c2 += mv * dr.z;
    }
    float* cb = &g_comb[(size_t)warp * 96 + lane * 3];
    cb[0] = c0; cb[1] = c1; cb[2] = c2;
}

// ---------------- K3a: spatial MLP + dv ----------------
__global__ void __launch_bounds__(256) k_spatial(
    const float* __restrict__ Wp1, const float* __restrict__ bp1,
    const float* __restrict__ Wp2, const float* __restrict__ bp2,
    const float* __restrict__ wvm)
{
    __shared__ __align__(16) float sWp1[32 * 64];
    __shared__ __align__(16) float sWp2[64 * 32];
    __shared__ float sbp1[64], sbp2[32], swv[32];
    for (int t = threadIdx.x; t < 2048; t += 256) sWp1[t] = Wp1[t];
    for (int t = threadIdx.x; t < 2048; t += 256) sWp2[t] = Wp2[t];
    if (threadIdx.x < 64) sbp1[threadIdx.x] = bp1[threadIdx.x];
    if (threadIdx.x < 32) sbp2[threadIdx.x] = bp2[threadIdx.x];
    if (threadIdx.x < 32) swv[threadIdx.x] = wvm[threadIdx.x];
    __syncthreads();

    int i = blockIdx.x * 256 + threadIdx.x;
    if (i >= NN) return;

    float invc = 1.f / fmaxf(g_cnt[i], 1.f);
    float n2[32];
    float dv0 = 0.f, dv1 = 0.f, dv2 = 0.f;
    {
        float val[96];
        const float4* cb = (const float4*)&g_comb[(size_t)i * 96];
        #pragma unroll
        for (int q = 0; q < 24; q++) {
            float4 v = __ldg(&cb[q]);
            val[4 * q] = v.x; val[4 * q + 1] = v.y; val[4 * q + 2] = v.z; val[4 * q + 3] = v.w;
        }
        #pragma unroll
        for (int c = 0; c < 32; c++) {
            float ax = val[3 * c] * invc, ay = val[3 * c + 1] * invc, az = val[3 * c + 2] * invc;
            n2[c] = ax * ax + ay * ay + az * az;
            float w = swv[c];
            dv0 += ax * w; dv1 += ay * w; dv2 += az * w;
        }
    }

    u64 s2acc[16];
    #pragma unroll
    for (int q = 0; q < 16; q++) s2acc[q] = 0ull;

    #pragma unroll 1
    for (int half = 0; half < 2; half++) {
        u64 acc[16];
        #pragma unroll
        for (int q = 0; q < 16; q++) acc[q] = 0ull;
        #pragma unroll 4
        for (int k = 0; k < 32; k++) {
            u64 nv = pk2(n2[k]);
            const ulonglong2* w = (const ulonglong2*)&sWp1[k * 64 + half * 32];
            #pragma unroll
            for (int q = 0; q < 8; q++) {
                ulonglong2 ww = w[q];
                fma2(acc[2 * q], nv, ww.x); fma2(acc[2 * q + 1], nv, ww.y);
            }
        }
        #pragma unroll 2
        for (int q = 0; q < 16; q++) {
            float2 p = upk(acc[q]);
            int row = half * 32 + 2 * q;
            float z0 = silu_(p.x + sbp1[row]);
            float z1 = silu_(p.y + sbp1[row + 1]);
            u64 a0 = pk2(z0), a1 = pk2(z1);
            const ulonglong2* w0 = (const ulonglong2*)&sWp2[row * 32];
            const ulonglong2* w1 = (const ulonglong2*)&sWp2[(row + 1) * 32];
            #pragma unroll
            for (int c = 0; c < 8; c++) {
                ulonglong2 ww = w0[c];
                fma2(s2acc[2 * c], a0, ww.x); fma2(s2acc[2 * c + 1], a0, ww.y);
            }
            #pragma unroll
            for (int c = 0; c < 8; c++) {
                ulonglong2 ww = w1[c];
                fma2(s2acc[2 * c], a1, ww.x); fma2(s2acc[2 * c + 1], a1, ww.y);
            }
        }
    }
    float4* sp4 = (float4*)&g_spa[(size_t)i * 32];
    #pragma unroll
    for (int q = 0; q < 8; q++) {
        float2 p0 = upk(s2acc[2 * q]);
        float2 p1 = upk(s2acc[2 * q + 1]);
        sp4[q] = make_float4(silu_(p0.x + sbp2[4 * q]),     silu_(p0.y + sbp2[4 * q + 1]),
                             silu_(p1.x + sbp2[4 * q + 2]), silu_(p1.y + sbp2[4 * q + 3]));
    }
    ((float4*)g_dv)[i] = make_float4(dv0, dv1, dv2, 0.f);
}

// ---------------- K3b: node MLP, 148 blocks x 338-node chunks (R9 monolithic) ----------------
#define NPB 338
__global__ void __launch_bounds__(512, 1) k_nodemlp(
    const float* __restrict__ h, const float* __restrict__ xx, const float* __restrict__ vv,
    const float* __restrict__ W1,  const float* __restrict__ b1,
    const float* __restrict__ W2,  const float* __restrict__ b2,
    const float* __restrict__ Wv1, const float* __restrict__ bv1,
    const float* __restrict__ Wv2,
    float* __restrict__ out)
{
    extern __shared__ __align__(16) float sw[];
    float* sW1  = sw;
    float* sW2  = sw + 28672;
    float* sWv1 = sW2 + 8192;
    float* sb1  = sWv1 + 2048;
    float* sb2  = sb1 + 128;
    float* sbv1 = sb2 + 64;
    float* sWv2 = sbv1 + 32;

    {
        float4* d = (float4*)sW1;
        const float4* s = (const float4*)W1;
        for (int t = threadIdx.x; t < 28672 / 4; t += 512) d[t] = s[t];
        d = (float4*)sW2; s = (const float4*)W2;
        for (int t = threadIdx.x; t < 8192 / 4; t += 512) d[t] = s[t];
        d = (float4*)sWv1; s = (const float4*)Wv1;
        for (int t = threadIdx.x; t < 2048 / 4; t += 512) d[t] = s[t];
        if (threadIdx.x < 128) sb1[threadIdx.x] = b1[threadIdx.x];
        if (threadIdx.x < 64)  sb2[threadIdx.x] = b2[threadIdx.x];
        if (threadIdx.x < 32)  sbv1[threadIdx.x] = bv1[threadIdx.x];
        if (threadIdx.x < 32)  sWv2[threadIdx.x] = Wv2[threadIdx.x];
    }
    __syncthreads();

    int i = blockIdx.x * NPB + threadIdx.x;
    if (threadIdx.x >= NPB || i >= NN) return;

    float4 dn = __ldg((const float4*)&g_denom[i * 4]);
    float inv4[4] = { 1.f / (dn.x + EPSF), 1.f / (dn.y + EPSF),
                      1.f / (dn.z + EPSF), 1.f / (dn.w + EPSF) };

    const float4* hs = (const float4*)(h + (size_t)i * 64);
    const float4* ss = (const float4*)&g_sem[(size_t)i * 128];
    const float4* ps = (const float4*)&g_spa[(size_t)i * 32];

    u64 acc2[32];
    #pragma unroll
    for (int q = 0; q < 32; q++) acc2[q] = 0ull;

    #pragma unroll 1
    for (int qtr = 0; qtr < 4; qtr++) {
        int co = qtr * 32;
        u64 acc[16];
        #pragma unroll
        for (int q = 0; q < 16; q++) acc[q] = 0ull;

        {
            float4 cur = __ldg(&hs[0]);
            #pragma unroll 1
            for (int k4 = 0; k4 < 16; k4++) {
                float4 nxt = (k4 < 15) ? __ldg(&hs[k4 + 1]) : make_float4(0.f, 0.f, 0.f, 0.f);
                float av[4] = {cur.x, cur.y, cur.z, cur.w};
                #pragma unroll
                for (int u = 0; u < 4; u++) {
                    u64 a = pk2(av[u]);
                    const ulonglong2* w = (const ulonglong2*)&sW1[(k4 * 4 + u) * 128 + co];
                    #pragma unroll
                    for (int q = 0; q < 8; q++) {
                        ulonglong2 ww = w[q];
                        fma2(acc[2 * q], a, ww.x); fma2(acc[2 * q + 1], a, ww.y);
                    }
                }
                cur = nxt;
            }
        }
        {
            float4 cur = __ldg(&ss[0]);
            #pragma unroll 1
            for (int k4 = 0; k4 < 32; k4++) {
                float4 nxt = (k4 < 31) ? __ldg(&ss[k4 + 1]) : make_float4(0.f, 0.f, 0.f, 0.f);
                float sc = inv4[k4 >> 3];
                float av[4] = {cur.x * sc, cur.y * sc, cur.z * sc, cur.w * sc};
                #pragma unroll
                for (int u = 0; u < 4; u++) {
                    u64 a = pk2(av[u]);
                    const ulonglong2* w = (const ulonglong2*)&sW1[(64 + k4 * 4 + u) * 128 + co];
                    #pragma unroll
                    for (int q = 0; q < 8; q++) {
                        ulonglong2 ww = w[q];
                        fma2(acc[2 * q], a, ww.x); fma2(acc[2 * q + 1], a, ww.y);
                    }
                }
                cur = nxt;
            }
        }
        {
            float4 cur = __ldg(&ps[0]);
            #pragma unroll 1
            for (int k4 = 0; k4 < 8; k4++) {
                float4 nxt = (k4 < 7) ? __ldg(&ps[k4 + 1]) : make_float4(0.f, 0.f, 0.f, 0.f);
                float av[4] = {cur.x, cur.y, cur.z, cur.w};
                #pragma unroll
                for (int u = 0; u < 4; u++) {
                    u64 a = pk2(av[u]);
                    const ulonglong2* w = (const ulonglong2*)&sW1[(192 + k4 * 4 + u) * 128 + co];
                    #pragma unroll
                    for (int q = 0; q < 8; q++) {
                        ulonglong2 ww = w[q];
                        fma2(acc[2 * q], a, ww.x); fma2(acc[2 * q + 1], a, ww.y);
                    }
                }
                cur = nxt;
            }
        }
        #pragma unroll 1
        for (int q = 0; q < 16; q++) {
            float2 p = upk(acc[q]);
            int row = co + 2 * q;
            float z0 = silu_(p.x + sb1[row]);
            float z1 = silu_(p.y + sb1[row + 1]);
            u64 a0 = pk2(z0), a1 = pk2(z1);
            const ulonglong2* w0 = (const ulonglong2*)&sW2[row * 64];
            const ulonglong2* w1 = (const ulonglong2*)&sW2[(row + 1) * 64];
            #pragma unroll
            for (int c = 0; c < 16; c++) {
                ulonglong2 ww = w0[c];
                fma2(acc2[2 * c], a0, ww.x); fma2(acc2[2 * c + 1], a0, ww.y);
            }
            #pragma unroll
            for (int c = 0; c < 16; c++) {
                ulonglong2 ww = w1[c];
                fma2(acc2[2 * c], a1, ww.x); fma2(acc2[2 * c + 1], a1, ww.y);
            }
        }
    }

    const float* hr = h + (size_t)i * 64;
    float2* outh = (float2*)&out[(size_t)i * 64];
    u64 ga[16];
    #pragma unroll
    for (int q = 0; q < 16; q++) ga[q] = 0ull;

    #pragma unroll 1
    for (int q = 0; q < 32; q++) {
        float2 p = upk(acc2[q]);
        float hu0 = __ldg(&hr[2 * q])     + silu_(p.x + sb2[2 * q]);
        float hu1 = __ldg(&hr[2 * q + 1]) + silu_(p.y + sb2[2 * q + 1]);
        outh[q] = make_float2(hu0, hu1);
        u64 a0 = pk2(hu0), a1 = pk2(hu1);
        const ulonglong2* w0 = (const ulonglong2*)&sWv1[(2 * q) * 32];
        const ulonglong2* w1 = (const ulonglong2*)&sWv1[(2 * q + 1) * 32];
        #pragma unroll
        for (int c = 0; c < 8; c++) {
            ulonglong2 ww = w0[c];
            fma2(ga[2 * c], a0, ww.x); fma2(ga[2 * c + 1], a0, ww.y);
        }
        #pragma unroll
        for (int c = 0; c < 8; c++) {
            ulonglong2 ww = w1[c];
            fma2(ga[2 * c], a1, ww.x); fma2(ga[2 * c + 1], a1, ww.y);
        }
    }

    float g = 0.f;
    #pragma unroll
    for (int q = 0; q < 16; q++) {
        float2 p = upk(ga[q]);
        g += silu_(p.x + sbv1[2 * q])     * sWv2[2 * q];
        g += silu_(p.y + sbv1[2 * q + 1]) * sWv2[2 * q + 1];
    }
    float gate = 2.f * (1.f / (1.f + __expf(-g)));

    float4 dv = __ldg((const float4*)&g_dv[i * 4]);
    float vx = gate * vv[3 * i]     + dv.x;
    float vy = gate * vv[3 * i + 1] + dv.y;
    float vz = gate * vv[3 * i + 2] + dv.z;
    float* outx = out + (size_t)NN * 64;
    float* outv = outx + (size_t)NN * 3;
    outx[3 * i]     = xx[3 * i]     + vx;
    outx[3 * i + 1] = xx[3 * i + 1] + vy;
    outx[3 * i + 2] = xx[3 * i + 2] + vz;
    outv[3 * i] = vx;  outv[3 * i + 1] = vy;  outv[3 * i + 2] = vz;
}

// ---------------- launch ----------------
extern "C" void kernel_launch(void* const* d_in, const int* in_sizes, int n_in,
                              void* d_out, int out_size) {
    const float* h   = (const float*)d_in[0];
    const float* x   = (const float*)d_in[1];
    const float* v   = (const float*)d_in[2];
    const int*   ii  = (const int*)d_in[3];
    const int*   jj  = (const int*)d_in[4];
    const float* Win = (const float*)d_in[5];
    const float* bin = (const float*)d_in[6];
    const float* Wh  = (const float*)d_in[7];
    const float* bh  = (const float*)d_in[8];
    const float* Wo  = (const float*)d_in[9];
    const float* bo  = (const float*)d_in[10];
    const float* Wa  = (const float*)d_in[11];
    const float* ba  = (const float*)d_in[12];
    const float* Wx  = (const float*)d_in[13];
    const float* W1  = (const float*)d_in[14];
    const float* b1  = (const float*)d_in[15];
    const float* W2  = (const float*)d_in[16];
    const float* b2  = (const float*)d_in[17];
    const float* Wp1 = (const float*)d_in[18];
    const float* bp1 = (const float*)d_in[19];
    const float* Wp2 = (const float*)d_in[20];
    const float* bp2 = (const float*)d_in[21];
    const float* Wv1 = (const float*)d_in[22];
    const float* bv1 = (const float*)d_in[23];
    const float* Wv2 = (const float*)d_in[24];
    const float* wvm = (const float*)d_in[25];
    float* out = (float*)d_out;

    const int NODE_SMEM = (28672 + 8192 + 2048 + 128 + 64 + 32 + 32) * 4;
    cudaFuncSetAttribute(k_nodemlp, cudaFuncAttributeMaxDynamicSharedMemorySize, NODE_SMEM);

    const int NSCAN = (NN + 255) / 256;   // 196

    k_zero<<<(NN + 256 + 255) / 256, 256>>>();
    k_count<<<(EE + 255) / 256, 256>>>(ii);
    k_pre<<<(NN + 255) / 256, 256>>>(h, Wh, Win, bin);
    k_scan_a<<<NSCAN, 256>>>();
    k_scan_b<<<1, 256>>>(NSCAN);
    k_scan_c<<<NSCAN, 256>>>();
    k_scatter<<<(EE + 255) / 256, 256>>>(ii, jj);
    k_edge1<<<(EE + 255) / 256, 256>>>(x, Wh, bh, Wo, bo, Wa, ba);
    k_agg1<<<(NN * 32 + 255) / 256, 256>>>();
    k_edge2<<<(EE / 2 + 255) / 256, 256>>>(Wx);
    k_agg2<<<(NN * 32 + 255) / 256, 256>>>();
    k_spatial<<<(NN + 255) / 256, 256>>>(Wp1, bp1, Wp2, bp2, wvm);
    k_nodemlp<<<148, 512, NODE_SMEM>>>(h, x, v, W1, b1, W2, b2,
                                       Wv1, bv1, Wv2, out);
}

// round 14
// speedup vs baseline: 1.1089x; 1.0051x over previous
#include <cuda_runtime.h>

#define NN 50000
#define EE 500000
#define EPSF 1e-8f

typedef unsigned long long u64;

// ---------------- scratch (device globals) ----------------
__device__ __align__(16) float g_hedge[EE * 32];   // he (pass1) then m (pass2)
__device__ __align__(16) float g_expl[EE * 4];
__device__ __align__(16) float g_dir[EE * 4];
__device__ __align__(16) float g_denom[NN * 4];
__device__ __align__(16) float g_cnt[NN];
__device__ __align__(16) float g_sem[NN * 128];
__device__ __align__(16) float g_comb[NN * 96];
__device__ __align__(16) float g_P1[NN * 64];
__device__ __align__(16) float g_P2[NN * 64];
__device__ __align__(16) float g_Q1[NN * 20];
__device__ __align__(16) float g_Q2[NN * 20];
__device__ __align__(16) float g_spa[NN * 32];
__device__ __align__(16) float g_dv[NN * 4];
__device__ __align__(16) float g_x4[NN * 4];       // packed coords {x,y,z,0}
// sorting infra
__device__ __align__(16) int g_icnt[NN + 256];
__device__ __align__(16) int g_rowstart[NN];
__device__ __align__(16) int g_woff[NN];
__device__ __align__(16) int2 g_sij[EE];
__device__ __align__(16) int g_bsum[256];
__device__ __align__(16) int g_boff[256];

// ---------------- helpers ----------------
__device__ __forceinline__ u64 pk2(float v) {
    u64 r; asm("mov.b64 %0,{%1,%1};" : "=l"(r) : "f"(v)); return r;
}
__device__ __forceinline__ u64 pk(float a, float b) {
    u64 r; asm("mov.b64 %0,{%1,%2};" : "=l"(r) : "f"(a), "f"(b)); return r;
}
__device__ __forceinline__ void fma2(u64 &d, u64 a, u64 b) {
    asm("fma.rn.f32x2 %0,%1,%2,%0;" : "+l"(d) : "l"(a), "l"(b));
}
__device__ __forceinline__ float2 upk(u64 v) {
    float2 f; asm("mov.b64 {%0,%1},%2;" : "=f"(f.x), "=f"(f.y) : "l"(v)); return f;
}
__device__ __forceinline__ float silu_(float z) { return z * (1.f / (1.f + __expf(-z))); }

// ---------------- K0: zero icnt ----------------
__global__ void k_zero() {
    int t = blockIdx.x * blockDim.x + threadIdx.x;
    if (t < NN + 256) g_icnt[t] = 0;
}

// ---------------- sort: histogram ----------------
__global__ void k_count(const int* __restrict__ idx_i) {
    int e = blockIdx.x * blockDim.x + threadIdx.x;
    if (e < EE) atomicAdd(&g_icnt[idx_i[e]], 1);
}

// ---------------- sort: block sums ----------------
__global__ void __launch_bounds__(256) k_scan_a() {
    __shared__ int s[256];
    int n = blockIdx.x * 256 + threadIdx.x;
    int v = (n < NN) ? g_icnt[n] : 0;
    s[threadIdx.x] = v;
    __syncthreads();
    #pragma unroll
    for (int off = 128; off > 0; off >>= 1) {
        if (threadIdx.x < off) s[threadIdx.x] += s[threadIdx.x + off];
        __syncthreads();
    }
    if (threadIdx.x == 0) g_bsum[blockIdx.x] = s[0];
}

// ---------------- sort: scan of block sums ----------------
__global__ void __launch_bounds__(256) k_scan_b(int nblocks) {
    __shared__ int s[256];
    int t = threadIdx.x;
    int v = (t < nblocks) ? g_bsum[t] : 0;
    s[t] = v;
    __syncthreads();
    #pragma unroll
    for (int off = 1; off < 256; off <<= 1) {
        int u = (t >= off) ? s[t - off] : 0;
        __syncthreads();
        s[t] += u;
        __syncthreads();
    }
    g_boff[t] = s[t] - v;   // exclusive
}

// ---------------- sort: per-block scan + offsets ----------------
__global__ void __launch_bounds__(256) k_scan_c() {
    __shared__ int s[256];
    int n = blockIdx.x * 256 + threadIdx.x;
    int c = (n < NN) ? g_icnt[n] : 0;
    int t = threadIdx.x;
    s[t] = c;
    __syncthreads();
    #pragma unroll
    for (int off = 1; off < 256; off <<= 1) {
        int u = (t >= off) ? s[t - off] : 0;
        __syncthreads();
        s[t] += u;
        __syncthreads();
    }
    if (n < NN) {
        int rs = g_boff[blockIdx.x] + s[t] - c;
        g_rowstart[n] = rs;
        g_woff[n] = rs;
        g_cnt[n] = (float)c;
    }
}

// ---------------- sort: scatter sorted (i,j) ----------------
__global__ void k_scatter(const int* __restrict__ idx_i, const int* __restrict__ idx_j) {
    int e = blockIdx.x * blockDim.x + threadIdx.x;
    if (e >= EE) return;
    int i = idx_i[e];
    int pos = atomicAdd(&g_woff[i], 1);
    g_sij[pos] = make_int2(i, idx_j[e]);
}

// ---------------- K_pre: per-node projections (R9 config) + x4 pack ----------------
__global__ void __launch_bounds__(256) k_pre(
    const float* __restrict__ h, const float* __restrict__ xx,
    const float* __restrict__ Wh, const float* __restrict__ Win,
    const float* __restrict__ bin)
{
    __shared__ __align__(16) float sWh[128 * 64];
    __shared__ __align__(16) float sWin[128 * 20];
    for (int t = threadIdx.x; t < 128 * 64; t += 256) sWh[t] = Wh[t];
    for (int t = threadIdx.x; t < 128 * 20; t += 256) sWin[t] = Win[t];
    __syncthreads();

    int i = blockIdx.x * 256 + threadIdx.x;
    if (i >= NN) return;

    ((float4*)g_x4)[i] = make_float4(xx[3 * i], xx[3 * i + 1], xx[3 * i + 2], 0.f);

    const float4* h4 = (const float4*)(h + (size_t)i * 64);

    #pragma unroll 1
    for (int g = 0; g < 2; g++) {
        u64 aP[32]; u64 aQ[10];
        #pragma unroll
        for (int q = 0; q < 32; q++) aP[q] = 0ull;
        #pragma unroll
        for (int q = 0; q < 10; q++) aQ[q] = 0ull;
        #pragma unroll 2
        for (int k4 = 0; k4 < 16; k4++) {
            float4 hv = __ldg(&h4[k4]);
            float hvv[4] = {hv.x, hv.y, hv.z, hv.w};
            #pragma unroll
            for (int u = 0; u < 4; u++) {
                int k = g * 64 + k4 * 4 + u;
                u64 a = pk2(hvv[u]);
                const ulonglong2* wr = (const ulonglong2*)&sWh[k * 64];
                #pragma unroll
                for (int t = 0; t < 16; t++) {
                    ulonglong2 ww = wr[t];
                    fma2(aP[2 * t], a, ww.x); fma2(aP[2 * t + 1], a, ww.y);
                }
                const u64* w2 = (const u64*)&sWin[k * 20];
                #pragma unroll
                for (int q = 0; q < 10; q++) fma2(aQ[q], a, w2[q]);
            }
        }
        float* P = (g == 0) ? &g_P1[(size_t)i * 64] : &g_P2[(size_t)i * 64];
        float* Q = (g == 0) ? &g_Q1[(size_t)i * 20] : &g_Q2[(size_t)i * 20];
        float4* P4 = (float4*)P;
        #pragma unroll
        for (int q = 0; q < 16; q++) {
            float2 p0 = upk(aP[2 * q]);
            float2 p1 = upk(aP[2 * q + 1]);
            P4[q] = make_float4(p0.x, p0.y, p1.x, p1.y);
        }
        #pragma unroll
        for (int q = 0; q < 10; q++) {
            float2 p = upk(aQ[q]);
            if (g == 0) {
                Q[2 * q]     = p.x + __ldg(&bin[2 * q]);
                Q[2 * q + 1] = p.y + __ldg(&bin[2 * q + 1]);
            } else {
                Q[2 * q] = p.x; Q[2 * q + 1] = p.y;
            }
        }
    }
}

// ---------------- K1: edge pass 1, low-register two-half pipeline ----------------
__global__ void __launch_bounds__(256, 2) k_edge1(
    const float* __restrict__ Wh,  const float* __restrict__ bh,
    const float* __restrict__ Wo,  const float* __restrict__ bo,
    const float* __restrict__ Wa,  const float* __restrict__ ba)
{
    __shared__ __align__(16) float sWr[20 * 64];
    __shared__ __align__(16) float sWl[64];
    __shared__ __align__(16) float sWo[64 * 32];
    __shared__ __align__(16) float sWa[32 * 4];
    __shared__ float sbh[64], sbo[32], sba[4];
    for (int t = threadIdx.x; t < 20 * 64; t += 256) sWr[t] = Wh[128 * 64 + t];
    for (int t = threadIdx.x; t < 64; t += 256)      sWl[t] = Wh[148 * 64 + t];
    for (int t = threadIdx.x; t < 64 * 32; t += 256) sWo[t] = Wo[t];
    for (int t = threadIdx.x; t < 128; t += 256)     sWa[t] = Wa[t];
    if (threadIdx.x < 64) sbh[threadIdx.x] = bh[threadIdx.x];
    if (threadIdx.x < 32) sbo[threadIdx.x] = bo[threadIdx.x];
    if (threadIdx.x < 4)  sba[threadIdx.x] = ba[threadIdx.x];
    __syncthreads();

    int t = blockIdx.x * 256 + threadIdx.x;
    if (t >= EE) return;
    int2 ij = g_sij[t];
    int i = ij.x, j = ij.y;

    float4 xi = __ldg(&((const float4*)g_x4)[i]);
    float4 xj = __ldg(&((const float4*)g_x4)[j]);
    float r0 = xj.x - xi.x;
    float r1 = xj.y - xi.y;
    float r2 = xj.z - xi.z;
    float d  = sqrtf(r0 * r0 + r1 * r1 + r2 * r2 + EPSF);
    float inv = 1.f / (d + EPSF);
    float dir0 = r0 * inv, dir1 = r1 * inv, dir2 = r2 * inv;

    float f20[20];
    {
        const float4* q1 = (const float4*)&g_Q1[(size_t)i * 20];
        const float4* q2 = (const float4*)&g_Q2[(size_t)j * 20];
        float ed  = __expf(-d);
        const float mu0  = 0.6065306597126334f;
        const float dmu  = (1.f - mu0) / 19.f;
        const float bb   = 0.1f * (1.f - mu0);
        const float beta = 1.f / (bb * bb);
        #pragma unroll
        for (int q = 0; q < 5; q++) {
            float4 a = __ldg(&q1[q]);
            float4 b = __ldg(&q2[q]);
            float qs[4] = {a.x + b.x, a.y + b.y, a.z + b.z, a.w + b.w};
            #pragma unroll
            for (int u = 0; u < 4; u++) {
                int r = q * 4 + u;
                float tt = ed - (mu0 + r * dmu);
                f20[r] = __expf(-beta * tt * tt) * qs[u];
            }
        }
    }

    u64 ho[16];
    #pragma unroll
    for (int q = 0; q < 16; q++) ho[q] = 0ull;

    const float4* p1b = (const float4*)&g_P1[(size_t)i * 64];
    const float4* p2b = (const float4*)&g_P2[(size_t)j * 64];

    #pragma unroll 1
    for (int half = 0; half < 2; half++) {
        int hc = half * 32;
        u64 a[16];
        #pragma unroll
        for (int q = 0; q < 8; q++) {
            float4 av = __ldg(&p1b[half * 8 + q]);
            float4 bv = __ldg(&p2b[half * 8 + q]);
            a[2 * q]     = pk(av.x + bv.x, av.y + bv.y);
            a[2 * q + 1] = pk(av.z + bv.z, av.w + bv.w);
        }
        #pragma unroll 4
        for (int r = 0; r < 20; r++) {
            u64 fv = pk2(f20[r]);
            const ulonglong2* wr = (const ulonglong2*)&sWr[r * 64 + hc];
            #pragma unroll
            for (int q = 0; q < 8; q++) {
                ulonglong2 ww = wr[q];
                fma2(a[2 * q], fv, ww.x); fma2(a[2 * q + 1], fv, ww.y);
            }
        }
        {
            u64 dv2 = pk2(d);
            const ulonglong2* wr = (const ulonglong2*)&sWl[hc];
            #pragma unroll
            for (int q = 0; q < 8; q++) {
                ulonglong2 ww = wr[q];
                fma2(a[2 * q], dv2, ww.x); fma2(a[2 * q + 1], dv2, ww.y);
            }
        }
        #pragma unroll 4
        for (int q = 0; q < 16; q++) {
            float2 p = upk(a[q]);
            int row = hc + 2 * q;
            float z0 = silu_(p.x + sbh[row]);
            float z1 = silu_(p.y + sbh[row + 1]);
            u64 h0 = pk2(z0), h1 = pk2(z1);
            const ulonglong2* w0 = (const ulonglong2*)&sWo[row * 32];
            const ulonglong2* w1 = (const ulonglong2*)&sWo[(row + 1) * 32];
            #pragma unroll
            for (int c = 0; c < 8; c++) {
                ulonglong2 ww = w0[c];
                fma2(ho[2 * c], h0, ww.x); fma2(ho[2 * c + 1], h0, ww.y);
            }
            #pragma unroll
            for (int c = 0; c < 8; c++) {
                ulonglong2 ww = w1[c];
                fma2(ho[2 * c], h1, ww.x); fma2(ho[2 * c + 1], h1, ww.y);
            }
        }
    }

    float he[32];
    #pragma unroll
    for (int q = 0; q < 16; q++) {
        float2 p = upk(ho[q]);
        he[2 * q]     = p.x + sbo[2 * q];
        he[2 * q + 1] = p.y + sbo[2 * q + 1];
    }

    float4* st = (float4*)&g_hedge[(size_t)t * 32];
    #pragma unroll
    for (int q = 0; q < 8; q++)
        st[q] = make_float4(he[4 * q], he[4 * q + 1], he[4 * q + 2], he[4 * q + 3]);

    float l0 = sba[0], l1 = sba[1], l2 = sba[2], l3 = sba[3];
    const float4* wa4 = (const float4*)sWa;
    #pragma unroll
    for (int c = 0; c < 32; c++) {
        float4 w = wa4[c];
        l0 += he[c] * w.x; l1 += he[c] * w.y; l2 += he[c] * w.z; l3 += he[c] * w.w;
    }
    float e0 = __expf(l0 > 0.f ? l0 : 2.f * (__expf(0.5f * l0) - 1.f));
    float e1 = __expf(l1 > 0.f ? l1 : 2.f * (__expf(0.5f * l1) - 1.f));
    float e2 = __expf(l2 > 0.f ? l2 : 2.f * (__expf(0.5f * l2) - 1.f));
    float e3 = __expf(l3 > 0.f ? l3 : 2.f * (__expf(0.5f * l3) - 1.f));

    ((float4*)g_expl)[t] = make_float4(e0, e1, e2, e3);
    ((float4*)g_dir)[t]  = make_float4(dir0, dir1, dir2, __int_as_float(i));
}

// ---------------- K_agg1: denom + sem, warp-per-node ----------------
__global__ void __launch_bounds__(256) k_agg1() {
    int warp = (blockIdx.x * 256 + threadIdx.x) >> 5;
    int lane = threadIdx.x & 31;
    if (warp >= NN) return;
    int s = g_rowstart[warp];
    int c = g_icnt[warp];

    float a0 = 0.f, a1 = 0.f, a2 = 0.f, a3 = 0.f;
    float d0 = 0.f, d1 = 0.f, d2 = 0.f, d3 = 0.f;
    #pragma unroll 4
    for (int k = 0; k < c; k++) {
        int t = s + k;
        float hev = g_hedge[(size_t)t * 32 + lane];
        float4 ex = ((const float4*)g_expl)[t];
        a0 += ex.x * hev; a1 += ex.y * hev; a2 += ex.z * hev; a3 += ex.w * hev;
        d0 += ex.x; d1 += ex.y; d2 += ex.z; d3 += ex.w;
    }
    float* sb = &g_sem[(size_t)warp * 128];
    sb[lane]      = a0;
    sb[32 + lane] = a1;
    sb[64 + lane] = a2;
    sb[96 + lane] = a3;
    if (lane == 0)
        ((float4*)g_denom)[warp] = make_float4(d0, d1, d2, d3);
}

// ---------------- K2: edge pass 2, TWO edges per thread ----------------
__global__ void __launch_bounds__(256) k_edge2(const float* __restrict__ Wx)
{
    __shared__ __align__(16) float sWx[128 * 32];
    for (int t = threadIdx.x; t < 128 * 32; t += 256) sWx[t] = Wx[t];
    __syncthreads();

    const int HALF = EE / 2;
    int t = blockIdx.x * 256 + threadIdx.x;
    if (t >= HALF) return;
    int tA = t, tB = t + HALF;

    float4 drA = ((const float4*)g_dir)[tA];
    float4 drB = ((const float4*)g_dir)[tB];
    int iA = __float_as_int(drA.w);
    int iB = __float_as_int(drB.w);

    float4 exA = ((const float4*)g_expl)[tA];
    float4 exB = ((const float4*)g_expl)[tB];
    float4 dnA = __ldg((const float4*)&g_denom[iA * 4]);
    float4 dnB = __ldg((const float4*)&g_denom[iB * 4]);
    float atA[4] = { exA.x / (dnA.x + EPSF), exA.y / (dnA.y + EPSF),
                     exA.z / (dnA.z + EPSF), exA.w / (dnA.w + EPSF) };
    float atB[4] = { exB.x / (dnB.x + EPSF), exB.y / (dnB.y + EPSF),
                     exB.z / (dnB.z + EPSF), exB.w / (dnB.w + EPSF) };

    float heA[32], heB[32];
    float4* hbA = (float4*)&g_hedge[(size_t)tA * 32];
    float4* hbB = (float4*)&g_hedge[(size_t)tB * 32];
    #pragma unroll
    for (int q = 0; q < 8; q++) {
        float4 v = hbA[q];
        heA[4 * q] = v.x; heA[4 * q + 1] = v.y; heA[4 * q + 2] = v.z; heA[4 * q + 3] = v.w;
        float4 w = hbB[q];
        heB[4 * q] = w.x; heB[4 * q + 1] = w.y; heB[4 * q + 2] = w.z; heB[4 * q + 3] = w.w;
    }

    u64 mxA[16], mxB[16];
    #pragma unroll
    for (int q = 0; q < 16; q++) { mxA[q] = 0ull; mxB[q] = 0ull; }

    #pragma unroll 4
    for (int k = 0; k < 128; k++) {
        float sA = atA[k >> 5] * heA[k & 31];
        float sB = atB[k >> 5] * heB[k & 31];
        u64 s2A = pk2(sA), s2B = pk2(sB);
        const ulonglong2* wr = (const ulonglong2*)&sWx[k * 32];
        #pragma unroll
        for (int q = 0; q < 8; q++) {
            ulonglong2 ww = wr[q];
            fma2(mxA[2 * q], s2A, ww.x); fma2(mxA[2 * q + 1], s2A, ww.y);
            fma2(mxB[2 * q], s2B, ww.x); fma2(mxB[2 * q + 1], s2B, ww.y);
        }
    }

    #pragma unroll
    for (int q = 0; q < 8; q++) {
        float2 p0 = upk(mxA[2 * q]);
        float2 p1 = upk(mxA[2 * q + 1]);
        hbA[q] = make_float4(tanhf(p0.x), tanhf(p0.y), tanhf(p1.x), tanhf(p1.y));
        float2 q0 = upk(mxB[2 * q]);
        float2 q1 = upk(mxB[2 * q + 1]);
        hbB[q] = make_float4(tanhf(q0.x), tanhf(q0.y), tanhf(q1.x), tanhf(q1.y));
    }
}

// ---------------- K_agg2: comb sums, warp-per-node ----------------
__global__ void __launch_bounds__(256) k_agg2() {
    int warp = (blockIdx.x * 256 + threadIdx.x) >> 5;
    int lane = threadIdx.x & 31;
    if (warp >= NN) return;
    int s = g_rowstart[warp];
    int c = g_icnt[warp];

    float c0 = 0.f, c1 = 0.f, c2 = 0.f;
    #pragma unroll 4
    for (int k = 0; k < c; k++) {
        int t = s + k;
        float mv = g_hedge[(size_t)t * 32 + lane];
        float4 dr = ((const float4*)g_dir)[t];
        c0 += mv * dr.x; c1 += mv * dr.y; c2 += mv * dr.z;
    }
    float* cb = &g_comb[(size_t)warp * 96 + lane * 3];
    cb[0] = c0; cb[1] = c1; cb[2] = c2;
}

// ---------------- K3a: spatial MLP + dv ----------------
__global__ void __launch_bounds__(256) k_spatial(
    const float* __restrict__ Wp1, const float* __restrict__ bp1,
    const float* __restrict__ Wp2, const float* __restrict__ bp2,
    const float* __restrict__ wvm)
{
    __shared__ __align__(16) float sWp1[32 * 64];
    __shared__ __align__(16) float sWp2[64 * 32];
    __shared__ float sbp1[64], sbp2[32], swv[32];
    for (int t = threadIdx.x; t < 2048; t += 256) sWp1[t] = Wp1[t];
    for (int t = threadIdx.x; t < 2048; t += 256) sWp2[t] = Wp2[t];
    if (threadIdx.x < 64) sbp1[threadIdx.x] = bp1[threadIdx.x];
    if (threadIdx.x < 32) sbp2[threadIdx.x] = bp2[threadIdx.x];
    if (threadIdx.x < 32) swv[threadIdx.x] = wvm[threadIdx.x];
    __syncthreads();

    int i = blockIdx.x * 256 + threadIdx.x;
    if (i >= NN) return;

    float invc = 1.f / fmaxf(g_cnt[i], 1.f);
    float n2[32];
    float dv0 = 0.f, dv1 = 0.f, dv2 = 0.f;
    {
        float val[96];
        const float4* cb = (const float4*)&g_comb[(size_t)i * 96];
        #pragma unroll
        for (int q = 0; q < 24; q++) {
            float4 v = __ldg(&cb[q]);
            val[4 * q] = v.x; val[4 * q + 1] = v.y; val[4 * q + 2] = v.z; val[4 * q + 3] = v.w;
        }
        #pragma unroll
        for (int c = 0; c < 32; c++) {
            float ax = val[3 * c] * invc, ay = val[3 * c + 1] * invc, az = val[3 * c + 2] * invc;
            n2[c] = ax * ax + ay * ay + az * az;
            float w = swv[c];
            dv0 += ax * w; dv1 += ay * w; dv2 += az * w;
        }
    }

    u64 s2acc[16];
    #pragma unroll
    for (int q = 0; q < 16; q++) s2acc[q] = 0ull;

    #pragma unroll 1
    for (int half = 0; half < 2; half++) {
        u64 acc[16];
        #pragma unroll
        for (int q = 0; q < 16; q++) acc[q] = 0ull;
        #pragma unroll 4
        for (int k = 0; k < 32; k++) {
            u64 nv = pk2(n2[k]);
            const ulonglong2* w = (const ulonglong2*)&sWp1[k * 64 + half * 32];
            #pragma unroll
            for (int q = 0; q < 8; q++) {
                ulonglong2 ww = w[q];
                fma2(acc[2 * q], nv, ww.x); fma2(acc[2 * q + 1], nv, ww.y);
            }
        }
        #pragma unroll 2
        for (int q = 0; q < 16; q++) {
            float2 p = upk(acc[q]);
            int row = half * 32 + 2 * q;
            float z0 = silu_(p.x + sbp1[row]);
            float z1 = silu_(p.y + sbp1[row + 1]);
            u64 a0 = pk2(z0), a1 = pk2(z1);
            const ulonglong2* w0 = (const ulonglong2*)&sWp2[row * 32];
            const ulonglong2* w1 = (const ulonglong2*)&sWp2[(row + 1) * 32];
            #pragma unroll
            for (int c = 0; c < 8; c++) {
                ulonglong2 ww = w0[c];
                fma2(s2acc[2 * c], a0, ww.x); fma2(s2acc[2 * c + 1], a0, ww.y);
            }
            #pragma unroll
            for (int c = 0; c < 8; c++) {
                ulonglong2 ww = w1[c];
                fma2(s2acc[2 * c], a1, ww.x); fma2(s2acc[2 * c + 1], a1, ww.y);
            }
        }
    }
    float4* sp4 = (float4*)&g_spa[(size_t)i * 32];
    #pragma unroll
    for (int q = 0; q < 8; q++) {
        float2 p0 = upk(s2acc[2 * q]);
        float2 p1 = upk(s2acc[2 * q + 1]);
        sp4[q] = make_float4(silu_(p0.x + sbp2[4 * q]),     silu_(p0.y + sbp2[4 * q + 1]),
                             silu_(p1.x + sbp2[4 * q + 2]), silu_(p1.y + sbp2[4 * q + 3]));
    }
    ((float4*)g_dv)[i] = make_float4(dv0, dv1, dv2, 0.f);
}

// ---------------- K3b: node MLP, 148 blocks x 338-node chunks (R9 monolithic) ----------------
#define NPB 338
__global__ void __launch_bounds__(512, 1) k_nodemlp(
    const float* __restrict__ h, const float* __restrict__ xx, const float* __restrict__ vv,
    const float* __restrict__ W1,  const float* __restrict__ b1,
    const float* __restrict__ W2,  const float* __restrict__ b2,
    const float* __restrict__ Wv1, const float* __restrict__ bv1,
    const float* __restrict__ Wv2,
    float* __restrict__ out)
{
    extern __shared__ __align__(16) float sw[];
    float* sW1  = sw;
    float* sW2  = sw + 28672;
    float* sWv1 = sW2 + 8192;
    float* sb1  = sWv1 + 2048;
    float* sb2  = sb1 + 128;
    float* sbv1 = sb2 + 64;
    float* sWv2 = sbv1 + 32;

    {
        float4* d = (float4*)sW1;
        const float4* s = (const float4*)W1;
        for (int t = threadIdx.x; t < 28672 / 4; t += 512) d[t] = s[t];
        d = (float4*)sW2; s = (const float4*)W2;
        for (int t = threadIdx.x; t < 8192 / 4; t += 512) d[t] = s[t];
        d = (float4*)sWv1; s = (const float4*)Wv1;
        for (int t = threadIdx.x; t < 2048 / 4; t += 512) d[t] = s[t];
        if (threadIdx.x < 128) sb1[threadIdx.x] = b1[threadIdx.x];
        if (threadIdx.x < 64)  sb2[threadIdx.x] = b2[threadIdx.x];
        if (threadIdx.x < 32)  sbv1[threadIdx.x] = bv1[threadIdx.x];
        if (threadIdx.x < 32)  sWv2[threadIdx.x] = Wv2[threadIdx.x];
    }
    __syncthreads();

    int i = blockIdx.x * NPB + threadIdx.x;
    if (threadIdx.x >= NPB || i >= NN) return;

    float4 dn = __ldg((const float4*)&g_denom[i * 4]);
    float inv4[4] = { 1.f / (dn.x + EPSF), 1.f / (dn.y + EPSF),
                      1.f / (dn.z + EPSF), 1.f / (dn.w + EPSF) };

    const float4* hs = (const float4*)(h + (size_t)i * 64);
    const float4* ss = (const float4*)&g_sem[(size_t)i * 128];
    const float4* ps = (const float4*)&g_spa[(size_t)i * 32];

    u64 acc2[32];
    #pragma unroll
    for (int q = 0; q < 32; q++) acc2[q] = 0ull;

    #pragma unroll 1
    for (int qtr = 0; qtr < 4; qtr++) {
        int co = qtr * 32;
        u64 acc[16];
        #pragma unroll
        for (int q = 0; q < 16; q++) acc[q] = 0ull;

        {
            float4 cur = __ldg(&hs[0]);
            #pragma unroll 1
            for (int k4 = 0; k4 < 16; k4++) {
                float4 nxt = (k4 < 15) ? __ldg(&hs[k4 + 1]) : make_float4(0.f, 0.f, 0.f, 0.f);
                float av[4] = {cur.x, cur.y, cur.z, cur.w};
                #pragma unroll
                for (int u = 0; u < 4; u++) {
                    u64 a = pk2(av[u]);
                    const ulonglong2* w = (const ulonglong2*)&sW1[(k4 * 4 + u) * 128 + co];
                    #pragma unroll
                    for (int q = 0; q < 8; q++) {
                        ulonglong2 ww = w[q];
                        fma2(acc[2 * q], a, ww.x); fma2(acc[2 * q + 1], a, ww.y);
                    }
                }
                cur = nxt;
            }
        }
        {
            float4 cur = __ldg(&ss[0]);
            #pragma unroll 1
            for (int k4 = 0; k4 < 32; k4++) {
                float4 nxt = (k4 < 31) ? __ldg(&ss[k4 + 1]) : make_float4(0.f, 0.f, 0.f, 0.f);
                float sc = inv4[k4 >> 3];
                float av[4] = {cur.x * sc, cur.y * sc, cur.z * sc, cur.w * sc};
                #pragma unroll
                for (int u = 0; u < 4; u++) {
                    u64 a = pk2(av[u]);
                    const ulonglong2* w = (const ulonglong2*)&sW1[(64 + k4 * 4 + u) * 128 + co];
                    #pragma unroll
                    for (int q = 0; q < 8; q++) {
                        ulonglong2 ww = w[q];
                        fma2(acc[2 * q], a, ww.x); fma2(acc[2 * q + 1], a, ww.y);
                    }
                }
                cur = nxt;
            }
        }
        {
            float4 cur = __ldg(&ps[0]);
            #pragma unroll 1
            for (int k4 = 0; k4 < 8; k4++) {
                float4 nxt = (k4 < 7) ? __ldg(&ps[k4 + 1]) : make_float4(0.f, 0.f, 0.f, 0.f);
                float av[4] = {cur.x, cur.y, cur.z, cur.w};
                #pragma unroll
                for (int u = 0; u < 4; u++) {
                    u64 a = pk2(av[u]);
                    const ulonglong2* w = (const ulonglong2*)&sW1[(192 + k4 * 4 + u) * 128 + co];
                    #pragma unroll
                    for (int q = 0; q < 8; q++) {
                        ulonglong2 ww = w[q];
                        fma2(acc[2 * q], a, ww.x); fma2(acc[2 * q + 1], a, ww.y);
                    }
                }
                cur = nxt;
            }
        }
        #pragma unroll 1
        for (int q = 0; q < 16; q++) {
            float2 p = upk(acc[q]);
            int row = co + 2 * q;
            float z0 = silu_(p.x + sb1[row]);
            float z1 = silu_(p.y + sb1[row + 1]);
            u64 a0 = pk2(z0), a1 = pk2(z1);
            const ulonglong2* w0 = (const ulonglong2*)&sW2[row * 64];
            const ulonglong2* w1 = (const ulonglong2*)&sW2[(row + 1) * 64];
            #pragma unroll
            for (int c = 0; c < 16; c++) {
                ulonglong2 ww = w0[c];
                fma2(acc2[2 * c], a0, ww.x); fma2(acc2[2 * c + 1], a0, ww.y);
            }
            #pragma unroll
            for (int c = 0; c < 16; c++) {
                ulonglong2 ww = w1[c];
                fma2(acc2[2 * c], a1, ww.x); fma2(acc2[2 * c + 1], a1, ww.y);
            }
        }
    }

    const float* hr = h + (size_t)i * 64;
    float2* outh = (float2*)&out[(size_t)i * 64];
    u64 ga[16];
    #pragma unroll
    for (int q = 0; q < 16; q++) ga[q] = 0ull;

    #pragma unroll 1
    for (int q = 0; q < 32; q++) {
        float2 p = upk(acc2[q]);
        float hu0 = __ldg(&hr[2 * q])     + silu_(p.x + sb2[2 * q]);
        float hu1 = __ldg(&hr[2 * q + 1]) + silu_(p.y + sb2[2 * q + 1]);
        outh[q] = make_float2(hu0, hu1);
        u64 a0 = pk2(hu0), a1 = pk2(hu1);
        const ulonglong2* w0 = (const ulonglong2*)&sWv1[(2 * q) * 32];
        const ulonglong2* w1 = (const ulonglong2*)&sWv1[(2 * q + 1) * 32];
        #pragma unroll
        for (int c = 0; c < 8; c++) {
            ulonglong2 ww = w0[c];
            fma2(ga[2 * c], a0, ww.x); fma2(ga[2 * c + 1], a0, ww.y);
        }
        #pragma unroll
        for (int c = 0; c < 8; c++) {
            ulonglong2 ww = w1[c];
            fma2(ga[2 * c], a1, ww.x); fma2(ga[2 * c + 1], a1, ww.y);
        }
    }

    float g = 0.f;
    #pragma unroll
    for (int q = 0; q < 16; q++) {
        float2 p = upk(ga[q]);
        g += silu_(p.x + sbv1[2 * q])     * sWv2[2 * q];
        g += silu_(p.y + sbv1[2 * q + 1]) * sWv2[2 * q + 1];
    }
    float gate = 2.f * (1.f / (1.f + __expf(-g)));

    float4 dv = __ldg((const float4*)&g_dv[i * 4]);
    float vx = gate * vv[3 * i]     + dv.x;
    float vy = gate * vv[3 * i + 1] + dv.y;
    float vz = gate * vv[3 * i + 2] + dv.z;
    float* outx = out + (size_t)NN * 64;
    float* outv = outx + (size_t)NN * 3;
    outx[3 * i]     = xx[3 * i]     + vx;
    outx[3 * i + 1] = xx[3 * i + 1] + vy;
    outx[3 * i + 2] = xx[3 * i + 2] + vz;
    outv[3 * i] = vx;  outv[3 * i + 1] = vy;  outv[3 * i + 2] = vz;
}

// ---------------- launch ----------------
extern "C" void kernel_launch(void* const* d_in, const int* in_sizes, int n_in,
                              void* d_out, int out_size) {
    const float* h   = (const float*)d_in[0];
    const float* x   = (const float*)d_in[1];
    const float* v   = (const float*)d_in[2];
    const int*   ii  = (const int*)d_in[3];
    const int*   jj  = (const int*)d_in[4];
    const float* Win = (const float*)d_in[5];
    const float* bin = (const float*)d_in[6];
    const float* Wh  = (const float*)d_in[7];
    const float* bh  = (const float*)d_in[8];
    const float* Wo  = (const float*)d_in[9];
    const float* bo  = (const float*)d_in[10];
    const float* Wa  = (const float*)d_in[11];
    const float* ba  = (const float*)d_in[12];
    const float* Wx  = (const float*)d_in[13];
    const float* W1  = (const float*)d_in[14];
    const float* b1  = (const float*)d_in[15];
    const float* W2  = (const float*)d_in[16];
    const float* b2  = (const float*)d_in[17];
    const float* Wp1 = (const float*)d_in[18];
    const float* bp1 = (const float*)d_in[19];
    const float* Wp2 = (const float*)d_in[20];
    const float* bp2 = (const float*)d_in[21];
    const float* Wv1 = (const float*)d_in[22];
    const float* bv1 = (const float*)d_in[23];
    const float* Wv2 = (const float*)d_in[24];
    const float* wvm = (const float*)d_in[25];
    float* out = (float*)d_out;

    const int NODE_SMEM = (28672 + 8192 + 2048 + 128 + 64 + 32 + 32) * 4;
    cudaFuncSetAttribute(k_nodemlp, cudaFuncAttributeMaxDynamicSharedMemorySize, NODE_SMEM);

    const int NSCAN = (NN + 255) / 256;   // 196

    k_zero<<<(NN + 256 + 255) / 256, 256>>>();
    k_count<<<(EE + 255) / 256, 256>>>(ii);
    k_pre<<<(NN + 255) / 256, 256>>>(h, x, Wh, Win, bin);
    k_scan_a<<<NSCAN, 256>>>();
    k_scan_b<<<1, 256>>>(NSCAN);
    k_scan_c<<<NSCAN, 256>>>();
    k_scatter<<<(EE + 255) / 256, 256>>>(ii, jj);
    k_edge1<<<(EE + 255) / 256, 256>>>(Wh, bh, Wo, bo, Wa, ba);
    k_agg1<<<(NN * 32 + 255) / 256, 256>>>();
    k_edge2<<<(EE / 2 + 255) / 256, 256>>>(Wx);
    k_agg2<<<(NN * 32 + 255) / 256, 256>>>();
    k_spatial<<<(NN + 255) / 256, 256>>>(Wp1, bp1, Wp2, bp2, wvm);
    k_nodemlp<<<148, 512, NODE_SMEM>>>(h, x, v, W1, b1, W2, b2,
                                       Wv1, bv1, Wv2, out);
}

// round 15
// speedup vs baseline: 1.1564x; 1.0428x over previous
#include <cuda_runtime.h>

#define NN 50000
#define EE 500000
#define EPSF 1e-8f

typedef unsigned long long u64;

// ---------------- scratch (device globals) ----------------
__device__ __align__(16) float g_hedge[EE * 32];   // he (pass1) then m (pass2)
__device__ __align__(16) float g_expl[EE * 4];
__device__ __align__(16) float g_dir[EE * 4];
__device__ __align__(16) float g_denom[NN * 4];
__device__ __align__(16) float g_cnt[NN];
__device__ __align__(16) float g_sem[NN * 128];
__device__ __align__(16) float g_comb[NN * 96];
__device__ __align__(16) float g_P1[NN * 64];
__device__ __align__(16) float g_P2[NN * 64];
__device__ __align__(16) float g_Q1[NN * 20];
__device__ __align__(16) float g_Q2[NN * 20];
__device__ __align__(16) float g_spa[NN * 32];
__device__ __align__(16) float g_dv[NN * 4];
__device__ __align__(16) float g_x4[NN * 4];       // packed coords {x,y,z,0}
// sorting infra
__device__ __align__(16) int g_icnt[NN + 256];
__device__ __align__(16) int g_rowstart[NN];
__device__ __align__(16) int g_woff[NN];
__device__ __align__(16) int2 g_sij[EE];
__device__ __align__(16) int g_bsum[256];
__device__ __align__(16) int g_boff[256];

// ---------------- helpers ----------------
__device__ __forceinline__ u64 pk2(float v) {
    u64 r; asm("mov.b64 %0,{%1,%1};" : "=l"(r) : "f"(v)); return r;
}
__device__ __forceinline__ u64 pk(float a, float b) {
    u64 r; asm("mov.b64 %0,{%1,%2};" : "=l"(r) : "f"(a), "f"(b)); return r;
}
__device__ __forceinline__ void fma2(u64 &d, u64 a, u64 b) {
    asm("fma.rn.f32x2 %0,%1,%2,%0;" : "+l"(d) : "l"(a), "l"(b));
}
__device__ __forceinline__ float2 upk(u64 v) {
    float2 f; asm("mov.b64 {%0,%1},%2;" : "=f"(f.x), "=f"(f.y) : "l"(v)); return f;
}
__device__ __forceinline__ float silu_(float z) { return z * (1.f / (1.f + __expf(-z))); }

// ---------------- K0: zero icnt ----------------
__global__ void k_zero() {
    int t = blockIdx.x * blockDim.x + threadIdx.x;
    if (t < NN + 256) g_icnt[t] = 0;
}

// ---------------- sort: histogram ----------------
__global__ void k_count(const int* __restrict__ idx_i) {
    int e = blockIdx.x * blockDim.x + threadIdx.x;
    if (e < EE) atomicAdd(&g_icnt[idx_i[e]], 1);
}

// ---------------- sort: block sums ----------------
__global__ void __launch_bounds__(256) k_scan_a() {
    __shared__ int s[256];
    int n = blockIdx.x * 256 + threadIdx.x;
    int v = (n < NN) ? g_icnt[n] : 0;
    s[threadIdx.x] = v;
    __syncthreads();
    #pragma unroll
    for (int off = 128; off > 0; off >>= 1) {
        if (threadIdx.x < off) s[threadIdx.x] += s[threadIdx.x + off];
        __syncthreads();
    }
    if (threadIdx.x == 0) g_bsum[blockIdx.x] = s[0];
}

// ---------------- sort: scan of block sums ----------------
__global__ void __launch_bounds__(256) k_scan_b(int nblocks) {
    __shared__ int s[256];
    int t = threadIdx.x;
    int v = (t < nblocks) ? g_bsum[t] : 0;
    s[t] = v;
    __syncthreads();
    #pragma unroll
    for (int off = 1; off < 256; off <<= 1) {
        int u = (t >= off) ? s[t - off] : 0;
        __syncthreads();
        s[t] += u;
        __syncthreads();
    }
    g_boff[t] = s[t] - v;   // exclusive
}

// ---------------- sort: per-block scan + offsets ----------------
__global__ void __launch_bounds__(256) k_scan_c() {
    __shared__ int s[256];
    int n = blockIdx.x * 256 + threadIdx.x;
    int c = (n < NN) ? g_icnt[n] : 0;
    int t = threadIdx.x;
    s[t] = c;
    __syncthreads();
    #pragma unroll
    for (int off = 1; off < 256; off <<= 1) {
        int u = (t >= off) ? s[t - off] : 0;
        __syncthreads();
        s[t] += u;
        __syncthreads();
    }
    if (n < NN) {
        int rs = g_boff[blockIdx.x] + s[t] - c;
        g_rowstart[n] = rs;
        g_woff[n] = rs;
        g_cnt[n] = (float)c;
    }
}

// ---------------- sort: scatter sorted (i,j) ----------------
__global__ void k_scatter(const int* __restrict__ idx_i, const int* __restrict__ idx_j) {
    int e = blockIdx.x * blockDim.x + threadIdx.x;
    if (e >= EE) return;
    int i = idx_i[e];
    int pos = atomicAdd(&g_woff[i], 1);
    g_sij[pos] = make_int2(i, idx_j[e]);
}

// ---------------- K_pre: per-node projections (R9 config) + x4 pack ----------------
__global__ void __launch_bounds__(256) k_pre(
    const float* __restrict__ h, const float* __restrict__ xx,
    const float* __restrict__ Wh, const float* __restrict__ Win,
    const float* __restrict__ bin)
{
    __shared__ __align__(16) float sWh[128 * 64];
    __shared__ __align__(16) float sWin[128 * 20];
    for (int t = threadIdx.x; t < 128 * 64; t += 256) sWh[t] = Wh[t];
    for (int t = threadIdx.x; t < 128 * 20; t += 256) sWin[t] = Win[t];
    __syncthreads();

    int i = blockIdx.x * 256 + threadIdx.x;
    if (i >= NN) return;

    ((float4*)g_x4)[i] = make_float4(xx[3 * i], xx[3 * i + 1], xx[3 * i + 2], 0.f);

    const float4* h4 = (const float4*)(h + (size_t)i * 64);

    #pragma unroll 1
    for (int g = 0; g < 2; g++) {
        u64 aP[32]; u64 aQ[10];
        #pragma unroll
        for (int q = 0; q < 32; q++) aP[q] = 0ull;
        #pragma unroll
        for (int q = 0; q < 10; q++) aQ[q] = 0ull;
        #pragma unroll 2
        for (int k4 = 0; k4 < 16; k4++) {
            float4 hv = __ldg(&h4[k4]);
            float hvv[4] = {hv.x, hv.y, hv.z, hv.w};
            #pragma unroll
            for (int u = 0; u < 4; u++) {
                int k = g * 64 + k4 * 4 + u;
                u64 a = pk2(hvv[u]);
                const ulonglong2* wr = (const ulonglong2*)&sWh[k * 64];
                #pragma unroll
                for (int t = 0; t < 16; t++) {
                    ulonglong2 ww = wr[t];
                    fma2(aP[2 * t], a, ww.x); fma2(aP[2 * t + 1], a, ww.y);
                }
                const u64* w2 = (const u64*)&sWin[k * 20];
                #pragma unroll
                for (int q = 0; q < 10; q++) fma2(aQ[q], a, w2[q]);
            }
        }
        float* P = (g == 0) ? &g_P1[(size_t)i * 64] : &g_P2[(size_t)i * 64];
        float* Q = (g == 0) ? &g_Q1[(size_t)i * 20] : &g_Q2[(size_t)i * 20];
        float4* P4 = (float4*)P;
        #pragma unroll
        for (int q = 0; q < 16; q++) {
            float2 p0 = upk(aP[2 * q]);
            float2 p1 = upk(aP[2 * q + 1]);
            P4[q] = make_float4(p0.x, p0.y, p1.x, p1.y);
        }
        #pragma unroll
        for (int q = 0; q < 10; q++) {
            float2 p = upk(aQ[q]);
            if (g == 0) {
                Q[2 * q]     = p.x + __ldg(&bin[2 * q]);
                Q[2 * q + 1] = p.y + __ldg(&bin[2 * q + 1]);
            } else {
                Q[2 * q] = p.x; Q[2 * q + 1] = p.y;
            }
        }
    }
}

// ---------------- K1: edge pass 1, low-register two-half pipeline ----------------
__global__ void __launch_bounds__(256, 2) k_edge1(
    const float* __restrict__ Wh,  const float* __restrict__ bh,
    const float* __restrict__ Wo,  const float* __restrict__ bo,
    const float* __restrict__ Wa,  const float* __restrict__ ba)
{
    __shared__ __align__(16) float sWr[20 * 64];
    __shared__ __align__(16) float sWl[64];
    __shared__ __align__(16) float sWo[64 * 32];
    __shared__ __align__(16) float sWa[32 * 4];
    __shared__ float sbh[64], sbo[32], sba[4];
    for (int t = threadIdx.x; t < 20 * 64; t += 256) sWr[t] = Wh[128 * 64 + t];
    for (int t = threadIdx.x; t < 64; t += 256)      sWl[t] = Wh[148 * 64 + t];
    for (int t = threadIdx.x; t < 64 * 32; t += 256) sWo[t] = Wo[t];
    for (int t = threadIdx.x; t < 128; t += 256)     sWa[t] = Wa[t];
    if (threadIdx.x < 64) sbh[threadIdx.x] = bh[threadIdx.x];
    if (threadIdx.x < 32) sbo[threadIdx.x] = bo[threadIdx.x];
    if (threadIdx.x < 4)  sba[threadIdx.x] = ba[threadIdx.x];
    __syncthreads();

    int t = blockIdx.x * 256 + threadIdx.x;
    if (t >= EE) return;
    int2 ij = g_sij[t];
    int i = ij.x, j = ij.y;

    float4 xi = __ldg(&((const float4*)g_x4)[i]);
    float4 xj = __ldg(&((const float4*)g_x4)[j]);
    float r0 = xj.x - xi.x;
    float r1 = xj.y - xi.y;
    float r2 = xj.z - xi.z;
    float d  = sqrtf(r0 * r0 + r1 * r1 + r2 * r2 + EPSF);
    float inv = 1.f / (d + EPSF);
    float dir0 = r0 * inv, dir1 = r1 * inv, dir2 = r2 * inv;

    float f20[20];
    {
        const float4* q1 = (const float4*)&g_Q1[(size_t)i * 20];
        const float4* q2 = (const float4*)&g_Q2[(size_t)j * 20];
        float ed  = __expf(-d);
        const float mu0  = 0.6065306597126334f;
        const float dmu  = (1.f - mu0) / 19.f;
        const float bb   = 0.1f * (1.f - mu0);
        const float beta = 1.f / (bb * bb);
        #pragma unroll
        for (int q = 0; q < 5; q++) {
            float4 a = __ldg(&q1[q]);
            float4 b = __ldg(&q2[q]);
            float qs[4] = {a.x + b.x, a.y + b.y, a.z + b.z, a.w + b.w};
            #pragma unroll
            for (int u = 0; u < 4; u++) {
                int r = q * 4 + u;
                float tt = ed - (mu0 + r * dmu);
                f20[r] = __expf(-beta * tt * tt) * qs[u];
            }
        }
    }

    u64 ho[16];
    #pragma unroll
    for (int q = 0; q < 16; q++) ho[q] = 0ull;

    const float4* p1b = (const float4*)&g_P1[(size_t)i * 64];
    const float4* p2b = (const float4*)&g_P2[(size_t)j * 64];

    #pragma unroll 1
    for (int half = 0; half < 2; half++) {
        int hc = half * 32;
        u64 a[16];
        #pragma unroll
        for (int q = 0; q < 8; q++) {
            float4 av = __ldg(&p1b[half * 8 + q]);
            float4 bv = __ldg(&p2b[half * 8 + q]);
            a[2 * q]     = pk(av.x + bv.x, av.y + bv.y);
            a[2 * q + 1] = pk(av.z + bv.z, av.w + bv.w);
        }
        #pragma unroll 4
        for (int r = 0; r < 20; r++) {
            u64 fv = pk2(f20[r]);
            const ulonglong2* wr = (const ulonglong2*)&sWr[r * 64 + hc];
            #pragma unroll
            for (int q = 0; q < 8; q++) {
                ulonglong2 ww = wr[q];
                fma2(a[2 * q], fv, ww.x); fma2(a[2 * q + 1], fv, ww.y);
            }
        }
        {
            u64 dv2 = pk2(d);
            const ulonglong2* wr = (const ulonglong2*)&sWl[hc];
            #pragma unroll
            for (int q = 0; q < 8; q++) {
                ulonglong2 ww = wr[q];
                fma2(a[2 * q], dv2, ww.x); fma2(a[2 * q + 1], dv2, ww.y);
            }
        }
        #pragma unroll 4
        for (int q = 0; q < 16; q++) {
            float2 p = upk(a[q]);
            int row = hc + 2 * q;
            float z0 = silu_(p.x + sbh[row]);
            float z1 = silu_(p.y + sbh[row + 1]);
            u64 h0 = pk2(z0), h1 = pk2(z1);
            const ulonglong2* w0 = (const ulonglong2*)&sWo[row * 32];
            const ulonglong2* w1 = (const ulonglong2*)&sWo[(row + 1) * 32];
            #pragma unroll
            for (int c = 0; c < 8; c++) {
                ulonglong2 ww = w0[c];
                fma2(ho[2 * c], h0, ww.x); fma2(ho[2 * c + 1], h0, ww.y);
            }
            #pragma unroll
            for (int c = 0; c < 8; c++) {
                ulonglong2 ww = w1[c];
                fma2(ho[2 * c], h1, ww.x); fma2(ho[2 * c + 1], h1, ww.y);
            }
        }
    }

    float he[32];
    #pragma unroll
    for (int q = 0; q < 16; q++) {
        float2 p = upk(ho[q]);
        he[2 * q]     = p.x + sbo[2 * q];
        he[2 * q + 1] = p.y + sbo[2 * q + 1];
    }

    float4* st = (float4*)&g_hedge[(size_t)t * 32];
    #pragma unroll
    for (int q = 0; q < 8; q++)
        st[q] = make_float4(he[4 * q], he[4 * q + 1], he[4 * q + 2], he[4 * q + 3]);

    float l0 = sba[0], l1 = sba[1], l2 = sba[2], l3 = sba[3];
    const float4* wa4 = (const float4*)sWa;
    #pragma unroll
    for (int c = 0; c < 32; c++) {
        float4 w = wa4[c];
        l0 += he[c] * w.x; l1 += he[c] * w.y; l2 += he[c] * w.z; l3 += he[c] * w.w;
    }
    float e0 = __expf(l0 > 0.f ? l0 : 2.f * (__expf(0.5f * l0) - 1.f));
    float e1 = __expf(l1 > 0.f ? l1 : 2.f * (__expf(0.5f * l1) - 1.f));
    float e2 = __expf(l2 > 0.f ? l2 : 2.f * (__expf(0.5f * l2) - 1.f));
    float e3 = __expf(l3 > 0.f ? l3 : 2.f * (__expf(0.5f * l3) - 1.f));

    ((float4*)g_expl)[t] = make_float4(e0, e1, e2, e3);
    ((float4*)g_dir)[t]  = make_float4(dir0, dir1, dir2, __int_as_float(i));
}

// ---------------- K_agg1: denom + sem, warp-per-node ----------------
__global__ void __launch_bounds__(256) k_agg1() {
    int warp = (blockIdx.x * 256 + threadIdx.x) >> 5;
    int lane = threadIdx.x & 31;
    if (warp >= NN) return;
    int s = g_rowstart[warp];
    int c = g_icnt[warp];

    float a0 = 0.f, a1 = 0.f, a2 = 0.f, a3 = 0.f;
    float d0 = 0.f, d1 = 0.f, d2 = 0.f, d3 = 0.f;
    #pragma unroll 2
    for (int k = 0; k < c; k++) {
        int t = s + k;
        float hev = g_hedge[(size_t)t * 32 + lane];
        float4 ex = ((const float4*)g_expl)[t];
        a0 += ex.x * hev; a1 += ex.y * hev; a2 += ex.z * hev; a3 += ex.w * hev;
        d0 += ex.x; d1 += ex.y; d2 += ex.z; d3 += ex.w;
    }
    float* sb = &g_sem[(size_t)warp * 128];
    sb[lane]      = a0;
    sb[32 + lane] = a1;
    sb[64 + lane] = a2;
    sb[96 + lane] = a3;
    if (lane == 0)
        ((float4*)g_denom)[warp] = make_float4(d0, d1, d2, d3);
}

// ---------------- K2: edge pass 2, TWO edges per thread ----------------
__global__ void __launch_bounds__(256) k_edge2(const float* __restrict__ Wx)
{
    __shared__ __align__(16) float sWx[128 * 32];
    for (int t = threadIdx.x; t < 128 * 32; t += 256) sWx[t] = Wx[t];
    __syncthreads();

    const int HALF = EE / 2;
    int t = blockIdx.x * 256 + threadIdx.x;
    if (t >= HALF) return;
    int tA = t, tB = t + HALF;

    float4 drA = ((const float4*)g_dir)[tA];
    float4 drB = ((const float4*)g_dir)[tB];
    int iA = __float_as_int(drA.w);
    int iB = __float_as_int(drB.w);

    float4 exA = ((const float4*)g_expl)[tA];
    float4 exB = ((const float4*)g_expl)[tB];
    float4 dnA = __ldg((const float4*)&g_denom[iA * 4]);
    float4 dnB = __ldg((const float4*)&g_denom[iB * 4]);
    float atA[4] = { exA.x / (dnA.x + EPSF), exA.y / (dnA.y + EPSF),
                     exA.z / (dnA.z + EPSF), exA.w / (dnA.w + EPSF) };
    float atB[4] = { exB.x / (dnB.x + EPSF), exB.y / (dnB.y + EPSF),
                     exB.z / (dnB.z + EPSF), exB.w / (dnB.w + EPSF) };

    float heA[32], heB[32];
    float4* hbA = (float4*)&g_hedge[(size_t)tA * 32];
    float4* hbB = (float4*)&g_hedge[(size_t)tB * 32];
    #pragma unroll
    for (int q = 0; q < 8; q++) {
        float4 v = hbA[q];
        heA[4 * q] = v.x; heA[4 * q + 1] = v.y; heA[4 * q + 2] = v.z; heA[4 * q + 3] = v.w;
        float4 w = hbB[q];
        heB[4 * q] = w.x; heB[4 * q + 1] = w.y; heB[4 * q + 2] = w.z; heB[4 * q + 3] = w.w;
    }

    u64 mxA[16], mxB[16];
    #pragma unroll
    for (int q = 0; q < 16; q++) { mxA[q] = 0ull; mxB[q] = 0ull; }

    #pragma unroll 4
    for (int k = 0; k < 128; k++) {
        float sA = atA[k >> 5] * heA[k & 31];
        float sB = atB[k >> 5] * heB[k & 31];
        u64 s2A = pk2(sA), s2B = pk2(sB);
        const ulonglong2* wr = (const ulonglong2*)&sWx[k * 32];
        #pragma unroll
        for (int q = 0; q < 8; q++) {
            ulonglong2 ww = wr[q];
            fma2(mxA[2 * q], s2A, ww.x); fma2(mxA[2 * q + 1], s2A, ww.y);
            fma2(mxB[2 * q], s2B, ww.x); fma2(mxB[2 * q + 1], s2B, ww.y);
        }
    }

    #pragma unroll
    for (int q = 0; q < 8; q++) {
        float2 p0 = upk(mxA[2 * q]);
        float2 p1 = upk(mxA[2 * q + 1]);
        hbA[q] = make_float4(tanhf(p0.x), tanhf(p0.y), tanhf(p1.x), tanhf(p1.y));
        float2 q0 = upk(mxB[2 * q]);
        float2 q1 = upk(mxB[2 * q + 1]);
        hbB[q] = make_float4(tanhf(q0.x), tanhf(q0.y), tanhf(q1.x), tanhf(q1.y));
    }
}

// ---------------- K_agg2: comb sums, warp-per-node ----------------
__global__ void __launch_bounds__(256) k_agg2() {
    int warp = (blockIdx.x * 256 + threadIdx.x) >> 5;
    int lane = threadIdx.x & 31;
    if (warp >= NN) return;
    int s = g_rowstart[warp];
    int c = g_icnt[warp];

    float c0 = 0.f, c1 = 0.f, c2 = 0.f;
    #pragma unroll 2
    for (int k = 0; k < c; k++) {
        int t = s + k;
        float mv = g_hedge[(size_t)t * 32 + lane];
        float4 dr = ((const float4*)g_dir)[t];
        c0 += mv * dr.x; c1 += mv * dr.y; c2 += mv * dr.z;
    }
    float* cb = &g_comb[(size_t)warp * 96 + lane * 3];
    cb[0] = c0; cb[1] = c1; cb[2] = c2;
}

// ---------------- K3a: spatial MLP + dv ----------------
__global__ void __launch_bounds__(256) k_spatial(
    const float* __restrict__ Wp1, const float* __restrict__ bp1,
    const float* __restrict__ Wp2, const float* __restrict__ bp2,
    const float* __restrict__ wvm)
{
    __shared__ __align__(16) float sWp1[32 * 64];
    __shared__ __align__(16) float sWp2[64 * 32];
    __shared__ float sbp1[64], sbp2[32], swv[32];
    for (int t = threadIdx.x; t < 2048; t += 256) sWp1[t] = Wp1[t];
    for (int t = threadIdx.x; t < 2048; t += 256) sWp2[t] = Wp2[t];
    if (threadIdx.x < 64) sbp1[threadIdx.x] = bp1[threadIdx.x];
    if (threadIdx.x < 32) sbp2[threadIdx.x] = bp2[threadIdx.x];
    if (threadIdx.x < 32) swv[threadIdx.x] = wvm[threadIdx.x];
    __syncthreads();

    int i = blockIdx.x * 256 + threadIdx.x;
    if (i >= NN) return;

    float invc = 1.f / fmaxf(g_cnt[i], 1.f);
    float n2[32];
    float dv0 = 0.f, dv1 = 0.f, dv2 = 0.f;
    {
        float val[96];
        const float4* cb = (const float4*)&g_comb[(size_t)i * 96];
        #pragma unroll
        for (int q = 0; q < 24; q++) {
            float4 v = __ldg(&cb[q]);
            val[4 * q] = v.x; val[4 * q + 1] = v.y; val[4 * q + 2] = v.z; val[4 * q + 3] = v.w;
        }
        #pragma unroll
        for (int c = 0; c < 32; c++) {
            float ax = val[3 * c] * invc, ay = val[3 * c + 1] * invc, az = val[3 * c + 2] * invc;
            n2[c] = ax * ax + ay * ay + az * az;
            float w = swv[c];
            dv0 += ax * w; dv1 += ay * w; dv2 += az * w;
        }
    }

    u64 s2acc[16];
    #pragma unroll
    for (int q = 0; q < 16; q++) s2acc[q] = 0ull;

    #pragma unroll 1
    for (int half = 0; half < 2; half++) {
        u64 acc[16];
        #pragma unroll
        for (int q = 0; q < 16; q++) acc[q] = 0ull;
        #pragma unroll 4
        for (int k = 0; k < 32; k++) {
            u64 nv = pk2(n2[k]);
            const ulonglong2* w = (const ulonglong2*)&sWp1[k * 64 + half * 32];
            #pragma unroll
            for (int q = 0; q < 8; q++) {
                ulonglong2 ww = w[q];
                fma2(acc[2 * q], nv, ww.x); fma2(acc[2 * q + 1], nv, ww.y);
            }
        }
        #pragma unroll 2
        for (int q = 0; q < 16; q++) {
            float2 p = upk(acc[q]);
            int row = half * 32 + 2 * q;
            float z0 = silu_(p.x + sbp1[row]);
            float z1 = silu_(p.y + sbp1[row + 1]);
            u64 a0 = pk2(z0), a1 = pk2(z1);
            const ulonglong2* w0 = (const ulonglong2*)&sWp2[row * 32];
            const ulonglong2* w1 = (const ulonglong2*)&sWp2[(row + 1) * 32];
            #pragma unroll
            for (int c = 0; c < 8; c++) {
                ulonglong2 ww = w0[c];
                fma2(s2acc[2 * c], a0, ww.x); fma2(s2acc[2 * c + 1], a0, ww.y);
            }
            #pragma unroll
            for (int c = 0; c < 8; c++) {
                ulonglong2 ww = w1[c];
                fma2(s2acc[2 * c], a1, ww.x); fma2(s2acc[2 * c + 1], a1, ww.y);
            }
        }
    }
    float4* sp4 = (float4*)&g_spa[(size_t)i * 32];
    #pragma unroll
    for (int q = 0; q < 8; q++) {
        float2 p0 = upk(s2acc[2 * q]);
        float2 p1 = upk(s2acc[2 * q + 1]);
        sp4[q] = make_float4(silu_(p0.x + sbp2[4 * q]),     silu_(p0.y + sbp2[4 * q + 1]),
                             silu_(p1.x + sbp2[4 * q + 2]), silu_(p1.y + sbp2[4 * q + 3]));
    }
    ((float4*)g_dv)[i] = make_float4(dv0, dv1, dv2, 0.f);
}

// ---------------- K3b: node MLP, 148 blocks x 338-node chunks (R9 monolithic) ----------------
#define NPB 338
__global__ void __launch_bounds__(512, 1) k_nodemlp(
    const float* __restrict__ h, const float* __restrict__ xx, const float* __restrict__ vv,
    const float* __restrict__ W1,  const float* __restrict__ b1,
    const float* __restrict__ W2,  const float* __restrict__ b2,
    const float* __restrict__ Wv1, const float* __restrict__ bv1,
    const float* __restrict__ Wv2,
    float* __restrict__ out)
{
    extern __shared__ __align__(16) float sw[];
    float* sW1  = sw;
    float* sW2  = sw + 28672;
    float* sWv1 = sW2 + 8192;
    float* sb1  = sWv1 + 2048;
    float* sb2  = sb1 + 128;
    float* sbv1 = sb2 + 64;
    float* sWv2 = sbv1 + 32;

    {
        float4* d = (float4*)sW1;
        const float4* s = (const float4*)W1;
        for (int t = threadIdx.x; t < 28672 / 4; t += 512) d[t] = s[t];
        d = (float4*)sW2; s = (const float4*)W2;
        for (int t = threadIdx.x; t < 8192 / 4; t += 512) d[t] = s[t];
        d = (float4*)sWv1; s = (const float4*)Wv1;
        for (int t = threadIdx.x; t < 2048 / 4; t += 512) d[t] = s[t];
        if (threadIdx.x < 128) sb1[threadIdx.x] = b1[threadIdx.x];
        if (threadIdx.x < 64)  sb2[threadIdx.x] = b2[threadIdx.x];
        if (threadIdx.x < 32)  sbv1[threadIdx.x] = bv1[threadIdx.x];
        if (threadIdx.x < 32)  sWv2[threadIdx.x] = Wv2[threadIdx.x];
    }
    __syncthreads();

    int i = blockIdx.x * NPB + threadIdx.x;
    if (threadIdx.x >= NPB || i >= NN) return;

    float4 dn = __ldg((const float4*)&g_denom[i * 4]);
    float inv4[4] = { 1.f / (dn.x + EPSF), 1.f / (dn.y + EPSF),
                      1.f / (dn.z + EPSF), 1.f / (dn.w + EPSF) };

    const float4* hs = (const float4*)(h + (size_t)i * 64);
    const float4* ss = (const float4*)&g_sem[(size_t)i * 128];
    const float4* ps = (const float4*)&g_spa[(size_t)i * 32];

    u64 acc2[32];
    #pragma unroll
    for (int q = 0; q < 32; q++) acc2[q] = 0ull;

    #pragma unroll 1
    for (int qtr = 0; qtr < 4; qtr++) {
        int co = qtr * 32;
        u64 acc[16];
        #pragma unroll
        for (int q = 0; q < 16; q++) acc[q] = 0ull;

        {
            float4 cur = __ldg(&hs[0]);
            #pragma unroll 1
            for (int k4 = 0; k4 < 16; k4++) {
                float4 nxt = (k4 < 15) ? __ldg(&hs[k4 + 1]) : make_float4(0.f, 0.f, 0.f, 0.f);
                float av[4] = {cur.x, cur.y, cur.z, cur.w};
                #pragma unroll
                for (int u = 0; u < 4; u++) {
                    u64 a = pk2(av[u]);
                    const ulonglong2* w = (const ulonglong2*)&sW1[(k4 * 4 + u) * 128 + co];
                    #pragma unroll
                    for (int q = 0; q < 8; q++) {
                        ulonglong2 ww = w[q];
                        fma2(acc[2 * q], a, ww.x); fma2(acc[2 * q + 1], a, ww.y);
                    }
                }
                cur = nxt;
            }
        }
        {
            float4 cur = __ldg(&ss[0]);
            #pragma unroll 1
            for (int k4 = 0; k4 < 32; k4++) {
                float4 nxt = (k4 < 31) ? __ldg(&ss[k4 + 1]) : make_float4(0.f, 0.f, 0.f, 0.f);
                float sc = inv4[k4 >> 3];
                float av[4] = {cur.x * sc, cur.y * sc, cur.z * sc, cur.w * sc};
                #pragma unroll
                for (int u = 0; u < 4; u++) {
                    u64 a = pk2(av[u]);
                    const ulonglong2* w = (const ulonglong2*)&sW1[(64 + k4 * 4 + u) * 128 + co];
                    #pragma unroll
                    for (int q = 0; q < 8; q++) {
                        ulonglong2 ww = w[q];
                        fma2(acc[2 * q], a, ww.x); fma2(acc[2 * q + 1], a, ww.y);
                    }
                }
                cur = nxt;
            }
        }
        {
            float4 cur = __ldg(&ps[0]);
            #pragma unroll 1
            for (int k4 = 0; k4 < 8; k4++) {
                float4 nxt = (k4 < 7) ? __ldg(&ps[k4 + 1]) : make_float4(0.f, 0.f, 0.f, 0.f);
                float av[4] = {cur.x, cur.y, cur.z, cur.w};
                #pragma unroll
                for (int u = 0; u < 4; u++) {
                    u64 a = pk2(av[u]);
                    const ulonglong2* w = (const ulonglong2*)&sW1[(192 + k4 * 4 + u) * 128 + co];
                    #pragma unroll
                    for (int q = 0; q < 8; q++) {
                        ulonglong2 ww = w[q];
                        fma2(acc[2 * q], a, ww.x); fma2(acc[2 * q + 1], a, ww.y);
                    }
                }
                cur = nxt;
            }
        }
        #pragma unroll 1
        for (int q = 0; q < 16; q++) {
            float2 p = upk(acc[q]);
            int row = co + 2 * q;
            float z0 = silu_(p.x + sb1[row]);
            float z1 = silu_(p.y + sb1[row + 1]);
            u64 a0 = pk2(z0), a1 = pk2(z1);
            const ulonglong2* w0 = (const ulonglong2*)&sW2[row * 64];
            const ulonglong2* w1 = (const ulonglong2*)&sW2[(row + 1) * 64];
            #pragma unroll
            for (int c = 0; c < 16; c++) {
                ulonglong2 ww = w0[c];
                fma2(acc2[2 * c], a0, ww.x); fma2(acc2[2 * c + 1], a0, ww.y);
            }
            #pragma unroll
            for (int c = 0; c < 16; c++) {
                ulonglong2 ww = w1[c];
                fma2(acc2[2 * c], a1, ww.x); fma2(acc2[2 * c + 1], a1, ww.y);
            }
        }
    }

    const float* hr = h + (size_t)i * 64;
    float2* outh = (float2*)&out[(size_t)i * 64];
    u64 ga[16];
    #pragma unroll
    for (int q = 0; q < 16; q++) ga[q] = 0ull;

    #pragma unroll 1
    for (int q = 0; q < 32; q++) {
        float2 p = upk(acc2[q]);
        float hu0 = __ldg(&hr[2 * q])     + silu_(p.x + sb2[2 * q]);
        float hu1 = __ldg(&hr[2 * q + 1]) + silu_(p.y + sb2[2 * q + 1]);
        outh[q] = make_float2(hu0, hu1);
        u64 a0 = pk2(hu0), a1 = pk2(hu1);
        const ulonglong2* w0 = (const ulonglong2*)&sWv1[(2 * q) * 32];
        const ulonglong2* w1 = (const ulonglong2*)&sWv1[(2 * q + 1) * 32];
        #pragma unroll
        for (int c = 0; c < 8; c++) {
            ulonglong2 ww = w0[c];
            fma2(ga[2 * c], a0, ww.x); fma2(ga[2 * c + 1], a0, ww.y);
        }
        #pragma unroll
        for (int c = 0; c < 8; c++) {
            ulonglong2 ww = w1[c];
            fma2(ga[2 * c], a1, ww.x); fma2(ga[2 * c + 1], a1, ww.y);
        }
    }

    float g = 0.f;
    #pragma unroll
    for (int q = 0; q < 16; q++) {
        float2 p = upk(ga[q]);
        g += silu_(p.x + sbv1[2 * q])     * sWv2[2 * q];
        g += silu_(p.y + sbv1[2 * q + 1]) * sWv2[2 * q + 1];
    }
    float gate = 2.f * (1.f / (1.f + __expf(-g)));

    float4 dv = __ldg((const float4*)&g_dv[i * 4]);
    float vx = gate * vv[3 * i]     + dv.x;
    float vy = gate * vv[3 * i + 1] + dv.y;
    float vz = gate * vv[3 * i + 2] + dv.z;
    float* outx = out + (size_t)NN * 64;
    float* outv = outx + (size_t)NN * 3;
    outx[3 * i]     = xx[3 * i]     + vx;
    outx[3 * i + 1] = xx[3 * i + 1] + vy;
    outx[3 * i + 2] = xx[3 * i + 2] + vz;
    outv[3 * i] = vx;  outv[3 * i + 1] = vy;  outv[3 * i + 2] = vz;
}

// ---------------- launch ----------------
extern "C" void kernel_launch(void* const* d_in, const int* in_sizes, int n_in,
                              void* d_out, int out_size) {
    const float* h   = (const float*)d_in[0];
    const float* x   = (const float*)d_in[1];
    const float* v   = (const float*)d_in[2];
    const int*   ii  = (const int*)d_in[3];
    const int*   jj  = (const int*)d_in[4];
    const float* Win = (const float*)d_in[5];
    const float* bin = (const float*)d_in[6];
    const float* Wh  = (const float*)d_in[7];
    const float* bh  = (const float*)d_in[8];
    const float* Wo  = (const float*)d_in[9];
    const float* bo  = (const float*)d_in[10];
    const float* Wa  = (const float*)d_in[11];
    const float* ba  = (const float*)d_in[12];
    const float* Wx  = (const float*)d_in[13];
    const float* W1  = (const float*)d_in[14];
    const float* b1  = (const float*)d_in[15];
    const float* W2  = (const float*)d_in[16];
    const float* b2  = (const float*)d_in[17];
    const float* Wp1 = (const float*)d_in[18];
    const float* bp1 = (const float*)d_in[19];
    const float* Wp2 = (const float*)d_in[20];
    const float* bp2 = (const float*)d_in[21];
    const float* Wv1 = (const float*)d_in[22];
    const float* bv1 = (const float*)d_in[23];
    const float* Wv2 = (const float*)d_in[24];
    const float* wvm = (const float*)d_in[25];
    float* out = (float*)d_out;

    const int NODE_SMEM = (28672 + 8192 + 2048 + 128 + 64 + 32 + 32) * 4;
    cudaFuncSetAttribute(k_nodemlp, cudaFuncAttributeMaxDynamicSharedMemorySize, NODE_SMEM);

    const int NSCAN = (NN + 255) / 256;   // 196

    k_zero<<<(NN + 256 + 255) / 256, 256>>>();
    k_count<<<(EE + 255) / 256, 256>>>(ii);
    k_pre<<<(NN + 255) / 256, 256>>>(h, x, Wh, Win, bin);
    k_scan_a<<<NSCAN, 256>>>();
    k_scan_b<<<1, 256>>>(NSCAN);
    k_scan_c<<<NSCAN, 256>>>();
    k_scatter<<<(EE + 255) / 256, 256>>>(ii, jj);
    k_edge1<<<(EE + 255) / 256, 256>>>(Wh, bh, Wo, bo, Wa, ba);
    k_agg1<<<(NN * 32 + 255) / 256, 256>>>();
    k_edge2<<<(EE / 2 + 255) / 256, 256>>>(Wx);
    k_agg2<<<(NN * 32 + 255) / 256, 256>>>();
    k_spatial<<<(NN + 255) / 256, 256>>>(Wp1, bp1, Wp2, bp2, wvm);
    k_nodemlp<<<148, 512, NODE_SMEM>>>(h, x, v, W1, b1, W2, b2,
                                       Wv1, bv1, Wv2, out);
}